// round 12
// baseline (speedup 1.0000x reference)
#include <cuda_runtime.h>
#include <math.h>
#include <cfloat>
#include <stdint.h>

// ---------------- constants ----------------
#define TAU_F   0.4f
#define ALPHA_F 1.0f
#define GAMMA_F 0.7f
#define DELTA_F 0.6f
#define MU_F    0.6f
#define NU_F    0.3f

#define N_  8192
#define E_  2048
#define D_  256
#define SAMP_ 100
#define MFN_  100
#define MHN_  200
#define ECAP_ 500
#define NSPL_ 64

// ---------------- scratch (device globals) ----------------
__device__ uint32_t g_w1th[D_ * D_], g_w1tl[D_ * D_];   // W transposed, split
__device__ uint32_t g_w2th[D_ * D_], g_w2tl[D_ * D_];
__device__ uint32_t g_tmph[N_ * D_], g_tmpl[N_ * D_];   // layer-1 out, split only
__device__ float g_z[N_ * D_];
__device__ uint32_t g_zh[N_ * D_], g_zl[N_ * D_];       // z split
__device__ float g_znpart[4][N_];
__device__ float g_edge_part[8][512 * D_];
__device__ int   g_cntp[8][512];
__device__ float g_etmp[512 * D_];
__device__ float g_hedges[512 * D_];
__device__ float g_hnpart[4][512];
__device__ float g_logits[512 * 512];
__device__ float g_sim[MHN_ * MHN_];
__device__ float g_attdot[MHN_ * MHN_];
__device__ float g_attm[MHN_ * NSPL_], g_atts[MHN_ * NSPL_];
__device__ float g_att[MHN_ * MHN_];
__device__ float g_lsem[MFN_ * NSPL_], g_lses[MFN_ * NSPL_];
__device__ float g_lse[MFN_];
__device__ float g_clrow[ECAP_];
__device__ float g_fnrow[MFN_], g_fncnt[MFN_];
__device__ float g_hnsum[MHN_], g_hncnt[MHN_];
__device__ int   g_nza[2048], g_nzb[2048];
__device__ float g_topo[SAMP_ * 2];

// ---------------- helpers ----------------
__device__ __forceinline__ float warp_sum(float v) {
#pragma unroll
    for (int o = 16; o > 0; o >>= 1) v += __shfl_xor_sync(0xffffffffu, v, o);
    return v;
}
__device__ __forceinline__ float warp_max(float v) {
#pragma unroll
    for (int o = 16; o > 0; o >>= 1) v = fmaxf(v, __shfl_xor_sync(0xffffffffu, v, o));
    return v;
}
__device__ __forceinline__ int warp_sum_i(int v) {
#pragma unroll
    for (int o = 16; o > 0; o >>= 1) v += __shfl_xor_sync(0xffffffffu, v, o);
    return v;
}
__device__ float block_sum(float v, float* sm) {
    int w = threadIdx.x >> 5, lane = threadIdx.x & 31, nw = blockDim.x >> 5;
    v = warp_sum(v);
    if (lane == 0) sm[w] = v;
    __syncthreads();
    float r = (threadIdx.x < nw) ? sm[threadIdx.x] : 0.f;
    if (w == 0) r = warp_sum(r);
    if (threadIdx.x == 0) sm[0] = r;
    __syncthreads();
    r = sm[0];
    __syncthreads();
    return r;
}
__device__ float block_max(float v, float* sm) {
    int w = threadIdx.x >> 5, lane = threadIdx.x & 31, nw = blockDim.x >> 5;
    v = warp_max(v);
    if (lane == 0) sm[w] = v;
    __syncthreads();
    float r = (threadIdx.x < nw) ? sm[threadIdx.x] : -FLT_MAX;
    if (w == 0) r = warp_max(r);
    if (threadIdx.x == 0) sm[0] = r;
    __syncthreads();
    r = sm[0];
    __syncthreads();
    return r;
}
__device__ __forceinline__ uint32_t f2tf32(float x) {
    uint32_t r;
    asm("cvt.rna.tf32.f32 %0, %1;" : "=r"(r) : "f"(x));
    return r;
}
__device__ __forceinline__ void mma_tf32(float* c, const uint32_t* a, const uint32_t* b) {
    asm volatile(
        "mma.sync.aligned.m16n8k8.row.col.f32.tf32.tf32.f32 "
        "{%0,%1,%2,%3}, {%4,%5,%6,%7}, {%8,%9}, {%0,%1,%2,%3};"
        : "+f"(c[0]), "+f"(c[1]), "+f"(c[2]), "+f"(c[3])
        : "r"(a[0]), "r"(a[1]), "r"(a[2]), "r"(a[3]), "r"(b[0]), "r"(b[1]));
}
__device__ __forceinline__ void ldsm4(uint32_t* r, uint32_t addr) {
    asm volatile("ldmatrix.sync.aligned.m8n8.x4.shared.b16 {%0,%1,%2,%3}, [%4];"
                 : "=r"(r[0]), "=r"(r[1]), "=r"(r[2]), "=r"(r[3]) : "r"(addr));
}
__device__ __forceinline__ uint32_t smem_u32(const void* p) {
    uint32_t a;
    asm("{ .reg .u64 t; cvta.to.shared.u64 t, %1; cvt.u32.u64 %0, t; }" : "=r"(a) : "l"(p));
    return a;
}
__device__ __forceinline__ void msmerge(float& m, float& s, float m2, float s2) {
    float M = fmaxf(m, m2);
    s = s * __expf(m - M) + s2 * __expf(m2 - M);
    m = M;
}
__device__ __forceinline__ void msadd(float& m, float& s, float v) {
    if (v <= m) s += __expf(v - m);
    else { s = s * __expf(m - v) + 1.f; m = v; }
}
__device__ __forceinline__ void split4(float4 v, uint32_t* hi, uint32_t* lo) {
    uint32_t h;
    h = f2tf32(v.x); hi[0] = h; lo[0] = f2tf32(v.x - __uint_as_float(h));
    h = f2tf32(v.y); hi[1] = h; lo[1] = f2tf32(v.y - __uint_as_float(h));
    h = f2tf32(v.z); hi[2] = h; lo[2] = f2tf32(v.z - __uint_as_float(h));
    h = f2tf32(v.w); hi[3] = h; lo[3] = f2tf32(v.w - __uint_as_float(h));
}

// ---------------- kernels ----------------

// pre-split MLP weights, transposed to [n][k]
__global__ void wsplit_kernel(const float* __restrict__ W1, const float* __restrict__ W2) {
    int i = blockIdx.x * 256 + threadIdx.x;   // 65536
    int n = i >> 8, k = i & 255;
    float x = W1[k * D_ + n];
    uint32_t h = f2tf32(x);
    g_w1th[i] = h;
    g_w1tl[i] = f2tf32(x - __uint_as_float(h));
    x = W2[k * D_ + n];
    h = f2tf32(x);
    g_w2th[i] = h;
    g_w2tl[i] = f2tf32(x - __uint_as_float(h));
}

__global__ void count_nz_kernel(const float4* __restrict__ a, const float4* __restrict__ b) {
    const int n4 = N_ * E_ / 4;
    int ca = 0, cb = 0;
    for (int i = blockIdx.x * blockDim.x + threadIdx.x; i < n4; i += gridDim.x * blockDim.x) {
        float4 x = a[i];
        ca += (x.x != 0.f) + (x.y != 0.f) + (x.z != 0.f) + (x.w != 0.f);
        float4 y = b[i];
        cb += (y.x != 0.f) + (y.y != 0.f) + (y.z != 0.f) + (y.w != 0.f);
    }
    __shared__ int sa[32], sb[32];
    int w = threadIdx.x >> 5, lane = threadIdx.x & 31;
    ca = warp_sum_i(ca); cb = warp_sum_i(cb);
    if (lane == 0) { sa[w] = ca; sb[w] = cb; }
    __syncthreads();
    if (w == 0) {
        int x = (lane < 8) ? sa[lane] : 0;
        int y = (lane < 8) ? sb[lane] : 0;
        x = warp_sum_i(x); y = warp_sum_i(y);
        if (lane == 0) { g_nza[blockIdx.x] = x; g_nzb[blockIdx.x] = y; }
    }
}

__global__ void topo_kernel(const float* __restrict__ Ho, const float* __restrict__ Hp) {
    __shared__ float hoi[128], hpi[128];
    __shared__ float sm[32];
    int i = blockIdx.x;
    int tid = threadIdx.x;
    if (tid < SAMP_) { hoi[tid] = Ho[i * E_ + tid]; hpi[tid] = Hp[i * E_ + tid]; }
    else             { hoi[tid] = 0.f; hpi[tid] = 0.f; }
    __syncthreads();
    int w = tid >> 5, lane = tid & 31;
    float dn2 = 0.f, on2 = 0.f;
    for (int j = w; j < SAMP_; j += 4) {
        float as = 0.f, aps = 0.f;
#pragma unroll
        for (int t = 0; t < 4; t++) {
            int k = lane + 32 * t;
            if (k < SAMP_) {
                as  += hoi[k] * Ho[j * E_ + k];
                aps += hpi[k] * Hp[j * E_ + k];
            }
        }
        as = warp_sum(as);
        aps = warp_sum(aps);
        if (lane == 0) {
            float d = as - aps;
            dn2 += d * d;
            on2 += as * as;
        }
    }
    float D2 = block_sum(dn2, sm);
    float O2 = block_sum(on2, sm);
    if (tid == 0) { g_topo[i * 2] = D2; g_topo[i * 2 + 1] = O2; }
}

// TF32 MLP GEMM with ldmatrix + pre-split operands.
// AFLOAT: A is float (split at load) else pre-split Ahg/Alg.
// WRITEF: also write float C. Always writes split output Chg/Clg.
template <bool RELU, bool NORM, bool AFLOAT, bool WRITEF>
__global__ void gemm_tf32_kernel(const float* __restrict__ A,
                                 const uint32_t* __restrict__ Ahg, const uint32_t* __restrict__ Alg,
                                 const uint32_t* __restrict__ Bth, const uint32_t* __restrict__ Btl,
                                 const float* __restrict__ bias,
                                 float* __restrict__ C,
                                 uint32_t* __restrict__ Chg, uint32_t* __restrict__ Clg) {
    __shared__ uint32_t Ah[128][20], Al[128][20];
    __shared__ uint32_t Bnh[64][20], Bnl[64][20];
    __shared__ float ssq[128][9];
    const int bm = blockIdx.x * 128, bn = blockIdx.y * 64;
    const int tid = threadIdx.x;
    const int lane = tid & 31, wid = tid >> 5;
    const int wm = wid >> 1, wn = wid & 1;
    const int g = lane >> 2, t = lane & 3;
    const uint32_t aH = smem_u32(&Ah[0][0]), aL = smem_u32(&Al[0][0]);
    const uint32_t bH = smem_u32(&Bnh[0][0]), bL = smem_u32(&Bnl[0][0]);
    float acc[2][4][4];
#pragma unroll
    for (int m = 0; m < 2; m++)
#pragma unroll
        for (int n = 0; n < 4; n++)
#pragma unroll
            for (int q = 0; q < 4; q++) acc[m][n][q] = 0.f;

    const int arow = (lane & 7) + ((lane >> 3) & 1) * 8;
    const int acol = ((lane >> 4) & 1) * 4;
    const int brow = (lane & 7) + ((lane >> 4) & 1) * 8;
    const int bcol = ((lane >> 3) & 1) * 4;

    for (int k0 = 0; k0 < D_; k0 += 16) {
#pragma unroll
        for (int l = 0; l < 2; l++) {
            int id = tid * 2 + l;
            int r = id >> 2, c4 = id & 3;
            if (AFLOAT) {
                float4 v = *(const float4*)&A[(bm + r) * D_ + k0 + c4 * 4];
                uint32_t hi[4], lo[4];
                split4(v, hi, lo);
                *(uint4*)&Ah[r][c4 * 4] = *(uint4*)hi;
                *(uint4*)&Al[r][c4 * 4] = *(uint4*)lo;
            } else {
                *(uint4*)&Ah[r][c4 * 4] = *(const uint4*)&Ahg[(bm + r) * D_ + k0 + c4 * 4];
                *(uint4*)&Al[r][c4 * 4] = *(const uint4*)&Alg[(bm + r) * D_ + k0 + c4 * 4];
            }
        }
        {
            int r = tid >> 2, c4 = tid & 3;   // n-row r (0..63)
            *(uint4*)&Bnh[r][c4 * 4] = *(const uint4*)&Bth[(bn + r) * D_ + k0 + c4 * 4];
            *(uint4*)&Bnl[r][c4 * 4] = *(const uint4*)&Btl[(bn + r) * D_ + k0 + c4 * 4];
        }
        __syncthreads();
#pragma unroll
        for (int ks = 0; ks < 16; ks += 8) {
            uint32_t ah[2][4], al[2][4], bh[2][4], bl[2][4];
#pragma unroll
            for (int m = 0; m < 2; m++) {
                uint32_t off = ((wm * 32 + m * 16 + arow) * 20 + ks + acol) * 4;
                ldsm4(ah[m], aH + off);
                ldsm4(al[m], aL + off);
            }
#pragma unroll
            for (int np = 0; np < 2; np++) {
                uint32_t off = ((wn * 32 + np * 16 + brow) * 20 + ks + bcol) * 4;
                ldsm4(bh[np], bH + off);
                ldsm4(bl[np], bL + off);
            }
#pragma unroll
            for (int m = 0; m < 2; m++)
#pragma unroll
                for (int n = 0; n < 4; n++) {
                    uint32_t* bhp = &bh[n >> 1][(n & 1) * 2];
                    uint32_t* blp = &bl[n >> 1][(n & 1) * 2];
                    mma_tf32(acc[m][n], ah[m], bhp);
                    mma_tf32(acc[m][n], ah[m], blp);
                    mma_tf32(acc[m][n], al[m], bhp);
                }
        }
        __syncthreads();
    }
    float sq[2][2] = {};
#pragma unroll
    for (int m = 0; m < 2; m++) {
        int row0 = bm + wm * 32 + m * 16 + g;
        int row1 = row0 + 8;
#pragma unroll
        for (int n = 0; n < 4; n++) {
            int col = bn + wn * 32 + n * 8 + t * 2;
            float b0 = bias[col], b1 = bias[col + 1];
            float v00 = acc[m][n][0] + b0, v01 = acc[m][n][1] + b1;
            float v10 = acc[m][n][2] + b0, v11 = acc[m][n][3] + b1;
            if (RELU) {
                v00 = fmaxf(v00, 0.f); v01 = fmaxf(v01, 0.f);
                v10 = fmaxf(v10, 0.f); v11 = fmaxf(v11, 0.f);
            }
            if (WRITEF) {
                *(float2*)&C[row0 * D_ + col] = make_float2(v00, v01);
                *(float2*)&C[row1 * D_ + col] = make_float2(v10, v11);
            }
            {
                uint32_t h0 = f2tf32(v00), h1 = f2tf32(v01);
                uint2 hu = make_uint2(h0, h1);
                uint2 lu = make_uint2(f2tf32(v00 - __uint_as_float(h0)),
                                      f2tf32(v01 - __uint_as_float(h1)));
                *(uint2*)&Chg[row0 * D_ + col] = hu;
                *(uint2*)&Clg[row0 * D_ + col] = lu;
                h0 = f2tf32(v10); h1 = f2tf32(v11);
                hu = make_uint2(h0, h1);
                lu = make_uint2(f2tf32(v10 - __uint_as_float(h0)),
                                f2tf32(v11 - __uint_as_float(h1)));
                *(uint2*)&Chg[row1 * D_ + col] = hu;
                *(uint2*)&Clg[row1 * D_ + col] = lu;
            }
            if (NORM) {
                sq[m][0] += v00 * v00 + v01 * v01;
                sq[m][1] += v10 * v10 + v11 * v11;
            }
        }
    }
    if (NORM) {
#pragma unroll
        for (int m = 0; m < 2; m++) {
            ssq[wm * 32 + m * 16 + g][wn * 4 + t] = sq[m][0];
            ssq[wm * 32 + m * 16 + g + 8][wn * 4 + t] = sq[m][1];
        }
        __syncthreads();
        if (tid < 128) {
            float s = 0.f;
#pragma unroll
            for (int q = 0; q < 8; q++) s += ssq[tid][q];
            g_znpart[blockIdx.y][bm + tid] = s;
        }
    }
}

// TF32 att/sim/lse GEMM, pre-split z (pure copy + ldmatrix + mma mainloop).
__global__ void attgemm_kernel() {
    __shared__ uint32_t Ah[64][20], Al[64][20];
    __shared__ uint32_t Bnh[128][20], Bnl[128][20];
    __shared__ float redm[64][2], reds[64][2];
    __shared__ float redm2[64][2], reds2[64][2];
    __shared__ float s_invi[64], s_invj[128];
    const int bm = blockIdx.x * 64;
    const int sp = blockIdx.y;
    const int j0 = sp * 128;
    const int tid = threadIdx.x;
    const int lane = tid & 31, wid = tid >> 5;
    const int wm = wid >> 1, wn = wid & 1;
    const int g = lane >> 2, t = lane & 3;
    const uint32_t aH = smem_u32(&Ah[0][0]), aL = smem_u32(&Al[0][0]);
    const uint32_t bH = smem_u32(&Bnh[0][0]), bL = smem_u32(&Bnl[0][0]);
    if (tid < 64) {
        int r = bm + tid;
        float s = g_znpart[0][r] + g_znpart[1][r] + g_znpart[2][r] + g_znpart[3][r];
        s_invi[tid] = 1.f / fmaxf(sqrtf(s), 1e-8f);
    } else if (tid >= 128) {
        int j = tid - 128;
        int r = j0 + j;
        float s = g_znpart[0][r] + g_znpart[1][r] + g_znpart[2][r] + g_znpart[3][r];
        s_invj[j] = 1.f / fmaxf(sqrtf(s), 1e-8f);
    }
    float acc[8][4];
#pragma unroll
    for (int n = 0; n < 8; n++)
#pragma unroll
        for (int q = 0; q < 4; q++) acc[n][q] = 0.f;

    const int arow = (lane & 7) + ((lane >> 3) & 1) * 8;
    const int acol = ((lane >> 4) & 1) * 4;
    const int brow = (lane & 7) + ((lane >> 4) & 1) * 8;
    const int bcol = ((lane >> 3) & 1) * 4;

    for (int k0 = 0; k0 < D_; k0 += 16) {
        {
            int r = tid >> 2, c4 = tid & 3;
            *(uint4*)&Ah[r][c4 * 4] = *(const uint4*)&g_zh[(bm + r) * D_ + k0 + c4 * 4];
            *(uint4*)&Al[r][c4 * 4] = *(const uint4*)&g_zl[(bm + r) * D_ + k0 + c4 * 4];
        }
#pragma unroll
        for (int l = 0; l < 2; l++) {
            int id = tid + 256 * l;
            int jr = id >> 2, c4 = id & 3;
            *(uint4*)&Bnh[jr][c4 * 4] = *(const uint4*)&g_zh[(j0 + jr) * D_ + k0 + c4 * 4];
            *(uint4*)&Bnl[jr][c4 * 4] = *(const uint4*)&g_zl[(j0 + jr) * D_ + k0 + c4 * 4];
        }
        __syncthreads();
#pragma unroll
        for (int ks = 0; ks < 16; ks += 8) {
            uint32_t ah[4], al[4];
            {
                uint32_t off = ((wm * 16 + arow) * 20 + ks + acol) * 4;
                ldsm4(ah, aH + off);
                ldsm4(al, aL + off);
            }
#pragma unroll
            for (int np = 0; np < 4; np++) {
                uint32_t b4h[4], b4l[4];
                uint32_t off = ((wn * 64 + np * 16 + brow) * 20 + ks + bcol) * 4;
                ldsm4(b4h, bH + off);
                ldsm4(b4l, bL + off);
                mma_tf32(acc[2 * np],     ah, b4h);
                mma_tf32(acc[2 * np],     ah, b4l);
                mma_tf32(acc[2 * np],     al, b4h);
                mma_tf32(acc[2 * np + 1], ah, b4h + 2);
                mma_tf32(acc[2 * np + 1], ah, b4l + 2);
                mma_tf32(acc[2 * np + 1], al, b4h + 2);
            }
        }
        __syncthreads();
    }
    const int rbase = wm * 16 + g;
    const int r0 = bm + rbase, r1 = r0 + 8;
    if (j0 < MHN_) {
        float i0v = s_invi[rbase], i1v = s_invi[rbase + 8];
#pragma unroll
        for (int n = 0; n < 8; n++) {
            int cl = wn * 64 + n * 8 + 2 * t;
            int j = j0 + cl;
            if (j < MHN_) {
                float jv = s_invj[cl];
                if (r0 < MHN_) { g_attdot[r0 * MHN_ + j] = acc[n][0]; g_sim[r0 * MHN_ + j] = acc[n][0] * i0v * jv; }
                if (r1 < MHN_) { g_attdot[r1 * MHN_ + j] = acc[n][2]; g_sim[r1 * MHN_ + j] = acc[n][2] * i1v * jv; }
            }
            if (j + 1 < MHN_) {
                float jv = s_invj[cl + 1];
                if (r0 < MHN_) { g_attdot[r0 * MHN_ + j + 1] = acc[n][1]; g_sim[r0 * MHN_ + j + 1] = acc[n][1] * i0v * jv; }
                if (r1 < MHN_) { g_attdot[r1 * MHN_ + j + 1] = acc[n][3]; g_sim[r1 * MHN_ + j + 1] = acc[n][3] * i1v * jv; }
            }
        }
    }
    {
        float m0 = -FLT_MAX, m1 = -FLT_MAX;
#pragma unroll
        for (int n = 0; n < 8; n++) {
            m0 = fmaxf(m0, fmaxf(acc[n][0], acc[n][1]));
            m1 = fmaxf(m1, fmaxf(acc[n][2], acc[n][3]));
        }
        float s0 = 0.f, s1 = 0.f;
#pragma unroll
        for (int n = 0; n < 8; n++) {
            s0 += __expf(acc[n][0] - m0) + __expf(acc[n][1] - m0);
            s1 += __expf(acc[n][2] - m1) + __expf(acc[n][3] - m1);
        }
#pragma unroll
        for (int o = 1; o <= 2; o <<= 1) {
            float mo = __shfl_xor_sync(0xffffffffu, m0, o);
            float so = __shfl_xor_sync(0xffffffffu, s0, o);
            msmerge(m0, s0, mo, so);
            mo = __shfl_xor_sync(0xffffffffu, m1, o);
            so = __shfl_xor_sync(0xffffffffu, s1, o);
            msmerge(m1, s1, mo, so);
        }
        if (t == 0) {
            redm[rbase][wn] = m0; reds[rbase][wn] = s0;
            redm[rbase + 8][wn] = m1; reds[rbase + 8][wn] = s1;
        }
    }
    if (bm < MFN_) {
        float vt0 = s_invi[rbase] * (1.f / TAU_F);
        float vt1 = s_invi[rbase + 8] * (1.f / TAU_F);
        float m2 = -FLT_MAX, s2 = 0.f, m3 = -FLT_MAX, s3 = 0.f;
#pragma unroll
        for (int n = 0; n < 8; n++) {
            int cl = wn * 64 + n * 8 + 2 * t;
            float j0v = s_invj[cl], j1v = s_invj[cl + 1];
            msadd(m2, s2, acc[n][0] * vt0 * j0v);
            msadd(m2, s2, acc[n][1] * vt0 * j1v);
            msadd(m3, s3, acc[n][2] * vt1 * j0v);
            msadd(m3, s3, acc[n][3] * vt1 * j1v);
        }
#pragma unroll
        for (int o = 1; o <= 2; o <<= 1) {
            float mo = __shfl_xor_sync(0xffffffffu, m2, o);
            float so = __shfl_xor_sync(0xffffffffu, s2, o);
            msmerge(m2, s2, mo, so);
            mo = __shfl_xor_sync(0xffffffffu, m3, o);
            so = __shfl_xor_sync(0xffffffffu, s3, o);
            msmerge(m3, s3, mo, so);
        }
        if (t == 0) {
            redm2[rbase][wn] = m2; reds2[rbase][wn] = s2;
            redm2[rbase + 8][wn] = m3; reds2[rbase + 8][wn] = s3;
        }
    }
    __syncthreads();
    if (tid < 64) {
        int i = bm + tid;
        if (i < MHN_) {
            float M = redm[tid][0], S = reds[tid][0];
            msmerge(M, S, redm[tid][1], reds[tid][1]);
            g_attm[i * NSPL_ + sp] = M;
            g_atts[i * NSPL_ + sp] = S;
        }
        if (i < MFN_) {
            float M = redm2[tid][0], S = reds2[tid][0];
            msmerge(M, S, redm2[tid][1], reds2[tid][1]);
            g_lsem[i * NSPL_ + sp] = M;
            g_lses[i * NSPL_ + sp] = S;
        }
    }
}

// cl logits GEMM
__global__ void clgemm_kernel() {
    __shared__ float As[16][68];
    __shared__ float Bs[16][132];
    __shared__ float s_invi[64], s_invj[128];
    const int bm = blockIdx.x * 64;
    const int j0 = blockIdx.y * 128;
    const int tid = threadIdx.x;
    const int tx = tid & 15, ty = tid >> 4;
    if (tid < 64) {
        int r = bm + tid;
        float s = g_znpart[0][r] + g_znpart[1][r] + g_znpart[2][r] + g_znpart[3][r];
        s_invi[tid] = 1.f / fmaxf(sqrtf(s), 1e-8f);
    }
    {
        int r = j0 + tid;
        float s = g_hnpart[0][r] + g_hnpart[1][r] + g_hnpart[2][r] + g_hnpart[3][r];
        s_invj[tid] = 1.f / fmaxf(sqrtf(s), 1e-8f);
    }
    float acc[8][8];
#pragma unroll
    for (int r = 0; r < 8; r++)
#pragma unroll
        for (int c = 0; c < 8; c++) acc[r][c] = 0.f;
    for (int k0 = 0; k0 < D_; k0 += 16) {
#pragma unroll
        for (int l = 0; l < 2; l++) {
            int id = tid * 2 + l;
            int r = id >> 2, c4 = id & 3;
            float4 v = *(const float4*)&g_z[(bm + r) * D_ + k0 + c4 * 4];
            As[c4 * 4 + 0][r] = v.x;
            As[c4 * 4 + 1][r] = v.y;
            As[c4 * 4 + 2][r] = v.z;
            As[c4 * 4 + 3][r] = v.w;
        }
#pragma unroll
        for (int l = 0; l < 4; l++) {
            int id = tid + 128 * l;
            int jr = id >> 2, c4 = id & 3;
            float4 v = *(const float4*)&g_hedges[(j0 + jr) * D_ + k0 + c4 * 4];
            Bs[c4 * 4 + 0][jr] = v.x;
            Bs[c4 * 4 + 1][jr] = v.y;
            Bs[c4 * 4 + 2][jr] = v.z;
            Bs[c4 * 4 + 3][jr] = v.w;
        }
        __syncthreads();
#pragma unroll
        for (int kk = 0; kk < 16; kk++) {
            float4 a0 = *(const float4*)&As[kk][ty * 8];
            float4 a1 = *(const float4*)&As[kk][ty * 8 + 4];
            float4 b0 = *(const float4*)&Bs[kk][tx * 8];
            float4 b1 = *(const float4*)&Bs[kk][tx * 8 + 4];
            float a[8] = {a0.x, a0.y, a0.z, a0.w, a1.x, a1.y, a1.z, a1.w};
            float b[8] = {b0.x, b0.y, b0.z, b0.w, b1.x, b1.y, b1.z, b1.w};
#pragma unroll
            for (int r = 0; r < 8; r++)
#pragma unroll
                for (int c = 0; c < 8; c++) acc[r][c] += a[r] * b[c];
        }
        __syncthreads();
    }
#pragma unroll
    for (int r = 0; r < 8; r++) {
        int i = bm + ty * 8 + r;
        if (i >= ECAP_) continue;
        float vi = s_invi[ty * 8 + r] * (1.f / TAU_F);
#pragma unroll
        for (int c = 0; c < 8; c += 2) {
            int j = j0 + tx * 8 + c;
            if (j < ECAP_ - 1) {
                *(float2*)&g_logits[i * 512 + j] =
                    make_float2(acc[r][c] * vi * s_invj[tx * 8 + c],
                                acc[r][c + 1] * vi * s_invj[tx * 8 + c + 1]);
            } else {
                if (j < ECAP_) g_logits[i * 512 + j] = acc[r][c] * vi * s_invj[tx * 8 + c];
                if (j + 1 < ECAP_) g_logits[i * 512 + j + 1] = acc[r][c + 1] * vi * s_invj[tx * 8 + c + 1];
            }
        }
    }
}

// Sparse edge aggregation (PROFILED this round)
__global__ void edge_part_kernel(const float* __restrict__ Hp, const float* __restrict__ z) {
    __shared__ float racc[8][4][256];
    __shared__ int rcnt[8][4];
    const int tid = threadIdx.x;
    const int lane = tid & 31, w = tid >> 5;
    const int e0 = blockIdx.x * 4, sp = blockIdx.y;
    float acc[4][8] = {};
    int cnt[4] = {0, 0, 0, 0};
    const int ibase = sp * 1024;
#pragma unroll 1
    for (int ic = 0; ic < 1024; ic += 256) {
        int i0 = ibase + ic;
        float4 v = *(const float4*)&Hp[(size_t)(i0 + tid) * E_ + e0];
        int m = (v.x > 0.f) | ((v.y > 0.f) << 1) | ((v.z > 0.f) << 2) | ((v.w > 0.f) << 3);
        unsigned b = __ballot_sync(0xffffffffu, m != 0);
        int rowbase = i0 + w * 32;
        while (b) {
            int src = __ffs(b) - 1;
            b &= b - 1;
            int mm = __shfl_sync(0xffffffffu, m, src);
            const float* zr = &z[(size_t)(rowbase + src) * D_];
            float zv[8];
#pragma unroll
            for (int t = 0; t < 8; t++) zv[t] = zr[lane + 32 * t];
            switch (mm) {
                case 1:
#pragma unroll
                    for (int t = 0; t < 8; t++) acc[0][t] += zv[t];
                    cnt[0]++; break;
                case 2:
#pragma unroll
                    for (int t = 0; t < 8; t++) acc[1][t] += zv[t];
                    cnt[1]++; break;
                case 4:
#pragma unroll
                    for (int t = 0; t < 8; t++) acc[2][t] += zv[t];
                    cnt[2]++; break;
                case 8:
#pragma unroll
                    for (int t = 0; t < 8; t++) acc[3][t] += zv[t];
                    cnt[3]++; break;
                default:
                    if (mm & 1) {
#pragma unroll
                        for (int t = 0; t < 8; t++) acc[0][t] += zv[t];
                        cnt[0]++;
                    }
                    if (mm & 2) {
#pragma unroll
                        for (int t = 0; t < 8; t++) acc[1][t] += zv[t];
                        cnt[1]++;
                    }
                    if (mm & 4) {
#pragma unroll
                        for (int t = 0; t < 8; t++) acc[2][t] += zv[t];
                        cnt[2]++;
                    }
                    if (mm & 8) {
#pragma unroll
                        for (int t = 0; t < 8; t++) acc[3][t] += zv[t];
                        cnt[3]++;
                    }
            }
        }
    }
#pragma unroll
    for (int e = 0; e < 4; e++)
#pragma unroll
        for (int t = 0; t < 8; t++) racc[w][e][lane + 32 * t] = acc[e][t];
    if (lane == 0) {
#pragma unroll
        for (int e = 0; e < 4; e++) rcnt[w][e] = cnt[e];
    }
    __syncthreads();
#pragma unroll
    for (int e = 0; e < 4; e++) {
        float s = 0.f;
#pragma unroll
        for (int q = 0; q < 8; q++) s += racc[q][e][tid];
        g_edge_part[sp][(e0 + e) * D_ + tid] = s;
    }
    if (tid < 4) {
        int c = 0;
#pragma unroll
        for (int q = 0; q < 8; q++) c += rcnt[q][tid];
        g_cntp[sp][e0 + tid] = c;
    }
}

// edge MLP layer 1 (mean fused)
__global__ void gemm64_e1_kernel(const float* __restrict__ B, const float* __restrict__ bias,
                                 float* __restrict__ C) {
    __shared__ float As[16][68];
    __shared__ float Bs[16][68];
    const int bm = blockIdx.x * 64, bn = blockIdx.y * 64;
    const int tid = threadIdx.x;
    const int tx = tid & 15, ty = tid >> 4;
    const int arow = bm + (tid >> 2);
    float cinv = 0.f;
    {
        int c = 0;
#pragma unroll
        for (int p = 0; p < 8; p++) c += g_cntp[p][arow];
        cinv = (c > 0 && arow < ECAP_) ? 1.f / (float)c : 0.f;
    }
    float acc[4][4] = {};
    for (int k0 = 0; k0 < D_; k0 += 16) {
        {
            int r = tid >> 2, c4 = tid & 3;
            float4 s = make_float4(0.f, 0.f, 0.f, 0.f);
#pragma unroll
            for (int p = 0; p < 8; p++) {
                float4 t = *(const float4*)&g_edge_part[p][arow * D_ + k0 + c4 * 4];
                s.x += t.x; s.y += t.y; s.z += t.z; s.w += t.w;
            }
            As[c4 * 4 + 0][r] = s.x * cinv;
            As[c4 * 4 + 1][r] = s.y * cinv;
            As[c4 * 4 + 2][r] = s.z * cinv;
            As[c4 * 4 + 3][r] = s.w * cinv;
        }
        {
            int r = tid >> 4, c4 = tid & 15;
            float4 v = *(const float4*)&B[(k0 + r) * D_ + bn + c4 * 4];
            *(float4*)&Bs[r][c4 * 4] = v;
        }
        __syncthreads();
#pragma unroll
        for (int kk = 0; kk < 16; kk++) {
            float a[4], b[4];
#pragma unroll
            for (int u = 0; u < 4; u++) a[u] = As[kk][ty * 4 + u];
#pragma unroll
            for (int u = 0; u < 4; u++) b[u] = Bs[kk][tx * 4 + u];
#pragma unroll
            for (int i = 0; i < 4; i++)
#pragma unroll
                for (int j = 0; j < 4; j++) acc[i][j] += a[i] * b[j];
        }
        __syncthreads();
    }
#pragma unroll
    for (int i = 0; i < 4; i++) {
        int row = bm + ty * 4 + i;
#pragma unroll
        for (int j = 0; j < 4; j++) {
            int col = bn + tx * 4 + j;
            C[row * D_ + col] = fmaxf(acc[i][j] + bias[col], 0.f);
        }
    }
}

// edge MLP layer 2 (hnorm partials fused)
__global__ void gemm64_e2_kernel(const float* __restrict__ A, const float* __restrict__ B,
                                 const float* __restrict__ bias, float* __restrict__ C) {
    __shared__ float As[16][68];
    __shared__ float Bs[16][68];
    __shared__ float ssq[64][17];
    const int bm = blockIdx.x * 64, bn = blockIdx.y * 64;
    const int tid = threadIdx.x;
    const int tx = tid & 15, ty = tid >> 4;
    float acc[4][4] = {};
    for (int k0 = 0; k0 < D_; k0 += 16) {
        {
            int r = tid >> 2, c4 = tid & 3;
            float4 v = *(const float4*)&A[(bm + r) * D_ + k0 + c4 * 4];
            As[c4 * 4 + 0][r] = v.x;
            As[c4 * 4 + 1][r] = v.y;
            As[c4 * 4 + 2][r] = v.z;
            As[c4 * 4 + 3][r] = v.w;
        }
        {
            int r = tid >> 4, c4 = tid & 15;
            float4 v = *(const float4*)&B[(k0 + r) * D_ + bn + c4 * 4];
            *(float4*)&Bs[r][c4 * 4] = v;
        }
        __syncthreads();
#pragma unroll
        for (int kk = 0; kk < 16; kk++) {
            float a[4], b[4];
#pragma unroll
            for (int u = 0; u < 4; u++) a[u] = As[kk][ty * 4 + u];
#pragma unroll
            for (int u = 0; u < 4; u++) b[u] = Bs[kk][tx * 4 + u];
#pragma unroll
            for (int i = 0; i < 4; i++)
#pragma unroll
                for (int j = 0; j < 4; j++) acc[i][j] += a[i] * b[j];
        }
        __syncthreads();
    }
#pragma unroll
    for (int i = 0; i < 4; i++) {
        int row = bm + ty * 4 + i;
        float sq = 0.f;
#pragma unroll
        for (int j = 0; j < 4; j++) {
            int col = bn + tx * 4 + j;
            float v = acc[i][j] + bias[col];
            C[row * D_ + col] = v;
            sq += v * v;
        }
        ssq[ty * 4 + i][tx] = sq;
    }
    __syncthreads();
    if (tid < 64) {
        float s = 0.f;
#pragma unroll
        for (int q = 0; q < 16; q++) s += ssq[tid][q];
        g_hnpart[blockIdx.y][bm + tid] = s;
    }
}

// merged finalize: att rows (0..199), lse (200)
__global__ void merge_kernel() {
    int b = blockIdx.x;
    if (b < MHN_) {
        int i = b;
        __shared__ float Ms, Ss;
        if (threadIdx.x == 0) {
            float M = -FLT_MAX;
            for (int p = 0; p < NSPL_; p++) M = fmaxf(M, g_attm[i * NSPL_ + p]);
            float S = 0.f;
            for (int p = 0; p < NSPL_; p++) S += g_atts[i * NSPL_ + p] * __expf(g_attm[i * NSPL_ + p] - M);
            Ms = M; Ss = S;
        }
        __syncthreads();
        for (int j = threadIdx.x; j < MHN_; j += blockDim.x)
            g_att[i * MHN_ + j] = __expf(g_attdot[i * MHN_ + j] - Ms) / Ss;
    } else {
        int i = threadIdx.x;
        if (i < MFN_) {
            float M = -FLT_MAX;
            for (int p = 0; p < NSPL_; p++) M = fmaxf(M, g_lsem[i * NSPL_ + p]);
            float S = 0.f;
            for (int p = 0; p < NSPL_; p++) S += g_lses[i * NSPL_ + p] * __expf(g_lsem[i * NSPL_ + p] - M);
            g_lse[i] = M + logf(S);
        }
    }
}

// fused losses
__global__ void losses_kernel(const float* __restrict__ Ho, const float* __restrict__ Hp) {
    __shared__ float sm[32];
    int b = blockIdx.x;
    int tid = threadIdx.x;
    if (b < ECAP_) {
        int i = b;
        float lm = -FLT_MAX;
        for (int j = tid; j < ECAP_; j += 256) lm = fmaxf(lm, g_logits[i * 512 + j]);
        float M = block_max(lm, sm);
        float ls = 0.f;
        for (int j = tid; j < ECAP_; j += 256) ls += __expf(g_logits[i * 512 + j] - M);
        float S = block_sum(ls, sm);
        if (tid == 0) g_clrow[i] = g_logits[i * 512 + i] - (M + logf(S));
    } else {
        int i = b - ECAP_;
        {
            int j = tid;
            bool act = j < MHN_;
            float simv = act ? g_sim[i * MHN_ + j] : 0.f;
            float attv = act ? g_att[i * MHN_ + j] : 1.f;
            bool mask = act && (j != i) && (simv > MU_F) && (attv < NU_F);
            float neg = -simv / TAU_F;
            float m = block_max(mask ? neg : -FLT_MAX, sm);
            if (m == -FLT_MAX) {
                if (tid == 0) { g_hnsum[i] = 0.f; g_hncnt[i] = 0.f; }
            } else {
                float s = block_sum(mask ? expf(neg - m) : 0.f, sm);
                float lse = m + logf(s);
                float wgt = fminf(simv / MU_F, 1.f);
                float pair = -wgt * (neg - lse);
                float ps = block_sum(mask ? pair : 0.f, sm);
                float pc = block_sum(mask ? 1.f : 0.f, sm);
                if (tid == 0) { g_hnsum[i] = ps; g_hncnt[i] = pc; }
            }
        }
        if (i < MFN_) {
            __shared__ unsigned char cand[128];
            __shared__ short clist[MFN_];
            __shared__ int ncand;
            if (tid < 128) cand[tid] = 0;
            __syncthreads();
            if (tid < MFN_) {
                bool g = (tid > i) && (g_sim[i * MHN_ + tid] > GAMMA_F)
                                   && (g_att[i * MHN_ + tid] > DELTA_F);
                cand[tid] = g ? 1 : 0;
            }
            __syncthreads();
            if (tid == 0) {
                int n = 0;
                for (int j = i + 1; j < MFN_; j++) if (cand[j]) clist[n++] = (short)j;
                ncand = n;
            }
            __syncthreads();
            int nc = ncand;
            float fsum = 0.f, fcnt = 0.f;
            for (int k = 0; k < nc; k++) {
                int j = clist[k];
                float ao = 0.f, ap = 0.f;
                for (int t = tid; t < E_; t += 256) {
                    ao += Ho[i * E_ + t] * Ho[j * E_ + t];
                    ap += Hp[i * E_ + t] * Hp[j * E_ + t];
                }
                ao = block_sum(ao, sm);
                ap = block_sum(ap, sm);
                if (ap == 0.f && ao > 0.f) {
                    fsum += -(g_sim[i * MHN_ + j] / TAU_F - g_lse[i]);
                    fcnt += 1.f;
                }
            }
            if (tid == 0) { g_fnrow[i] = fsum; g_fncnt[i] = fcnt; }
        }
    }
}

// final combine
__global__ void final_kernel(const float* __restrict__ bw, float* __restrict__ out) {
    __shared__ float sm[32];
    int tid = threadIdx.x;
    float v = 0.f;
    for (int i = tid; i < ECAP_; i += 512) v += g_clrow[i];
    float clsum = block_sum(v, sm);
    v = 0.f; float c = 0.f;
    for (int i = tid; i < MFN_; i += 512) { v += g_fnrow[i]; c += g_fncnt[i]; }
    float fnsum = block_sum(v, sm);
    float fncnt = block_sum(c, sm);
    v = 0.f; c = 0.f;
    for (int i = tid; i < MHN_; i += 512) { v += g_hnsum[i]; c += g_hncnt[i]; }
    float hnsum = block_sum(v, sm);
    float hncnt = block_sum(c, sm);
    float d2 = 0.f, o2 = 0.f;
    for (int i = tid; i < SAMP_; i += 512) { d2 += g_topo[i * 2]; o2 += g_topo[i * 2 + 1]; }
    float D2 = block_sum(d2, sm);
    float O2 = block_sum(o2, sm);
    float za = 0.f, zb = 0.f;
    for (int i = tid; i < 2048; i += 512) { za += (float)g_nza[i]; zb += (float)g_nzb[i]; }
    float NZ = block_sum(za, sm);
    float NZP = block_sum(zb, sm);
    if (tid == 0) {
        float cl_loss = -clsum / (float)ECAP_;
        float fn_loss = (fncnt > 0.f) ? fnsum / fmaxf(fncnt, 1.f) : 0.f;
        float hard_loss = (hncnt > 0.f) ? hnsum / fmaxf(hncnt, 1.f) : 0.f;
        float sparsity = (NZ > 0.f) ? NZP / fmaxf(NZ, 1.f) : 1.f;
        float dn = sqrtf(D2), on = sqrtf(O2);
        float topo = (on > 0.f) ? expf(-ALPHA_F * dn / fmaxf(on, 1e-12f)) : 1.f;
        float retention = sparsity * topo;
        out[0] = bw[0] * (retention * cl_loss + fn_loss + hard_loss);
    }
}

// ---------------- launch ----------------
extern "C" void kernel_launch(void* const* d_in, const int* in_sizes, int n_in,
                              void* d_out, int out_size) {
    (void)in_sizes; (void)n_in; (void)out_size;
    const float* Ho  = (const float*)d_in[0];
    const float* Hp  = (const float*)d_in[1];
    const float* ne  = (const float*)d_in[2];
    const float* bw  = (const float*)d_in[3];
    const float* Wn1 = (const float*)d_in[4];
    const float* bn1 = (const float*)d_in[5];
    const float* Wn2 = (const float*)d_in[6];
    const float* bn2 = (const float*)d_in[7];
    const float* We1 = (const float*)d_in[8];
    const float* be1 = (const float*)d_in[9];
    const float* We2 = (const float*)d_in[10];
    const float* be2 = (const float*)d_in[11];
    float* out = (float*)d_out;

    void *p;
    float *p_z, *p_etmp, *p_hedges;
    uint32_t *p_w1th, *p_w1tl, *p_w2th, *p_w2tl, *p_tmph, *p_tmpl, *p_zh, *p_zl;
    cudaGetSymbolAddress(&p, g_z);      p_z      = (float*)p;
    cudaGetSymbolAddress(&p, g_etmp);   p_etmp   = (float*)p;
    cudaGetSymbolAddress(&p, g_hedges); p_hedges = (float*)p;
    cudaGetSymbolAddress(&p, g_w1th);   p_w1th   = (uint32_t*)p;
    cudaGetSymbolAddress(&p, g_w1tl);   p_w1tl   = (uint32_t*)p;
    cudaGetSymbolAddress(&p, g_w2th);   p_w2th   = (uint32_t*)p;
    cudaGetSymbolAddress(&p, g_w2tl);   p_w2tl   = (uint32_t*)p;
    cudaGetSymbolAddress(&p, g_tmph);   p_tmph   = (uint32_t*)p;
    cudaGetSymbolAddress(&p, g_tmpl);   p_tmpl   = (uint32_t*)p;
    cudaGetSymbolAddress(&p, g_zh);     p_zh     = (uint32_t*)p;
    cudaGetSymbolAddress(&p, g_zl);     p_zl     = (uint32_t*)p;

    // idx 0: weight pre-split (transposed)
    wsplit_kernel<<<256, 256>>>(Wn1, Wn2);

    // idx 1-2: node MLP (L1: split A at load, split output; L2: all pre-split)
    gemm_tf32_kernel<true,  false, true,  false><<<dim3(64, 4), 256>>>(
        ne, nullptr, nullptr, p_w1th, p_w1tl, bn1, nullptr, p_tmph, p_tmpl);
    gemm_tf32_kernel<false, true,  false, true ><<<dim3(64, 4), 256>>>(
        nullptr, p_tmph, p_tmpl, p_w2th, p_w2tl, bn2, p_z, p_zh, p_zl);

    // idx 3: edge aggregation (PROFILED this round)
    edge_part_kernel<<<dim3(ECAP_ / 4, 8), 256>>>(Hp, p_z);

    // idx 4: count_nz
    count_nz_kernel<<<2048, 256>>>((const float4*)Ho, (const float4*)Hp);

    // idx 5: att/sim/lse (pre-split z)
    attgemm_kernel<<<dim3(4, NSPL_), 256>>>();

    // idx 6: topo
    topo_kernel<<<SAMP_, 128>>>(Ho, Hp);

    // idx 7-8: edge MLP
    gemm64_e1_kernel<<<dim3(8, 4), 256>>>(We1, be1, p_etmp);
    gemm64_e2_kernel<<<dim3(8, 4), 256>>>(p_etmp, We2, be2, p_hedges);

    // idx 9: merge finalizers
    merge_kernel<<<MHN_ + 1, 256>>>();

    // idx 10: cl logits GEMM
    clgemm_kernel<<<dim3(8, 4), 128>>>();

    // idx 11: fused losses
    losses_kernel<<<ECAP_ + MHN_, 256>>>(Ho, Hp);

    // idx 12: final combine
    final_kernel<<<1, 512>>>(bw, out);
}

// round 13
// speedup vs baseline: 1.2507x; 1.2507x over previous
#include <cuda_runtime.h>
#include <math.h>
#include <cfloat>
#include <stdint.h>

// ---------------- constants ----------------
#define TAU_F   0.4f
#define ALPHA_F 1.0f
#define GAMMA_F 0.7f
#define DELTA_F 0.6f
#define MU_F    0.6f
#define NU_F    0.3f

#define N_  8192
#define E_  2048
#define D_  256
#define SAMP_ 100
#define MFN_  100
#define MHN_  200
#define ECAP_ 500
#define NSPL_ 64

// ---------------- scratch (device globals) ----------------
__device__ float g_tmp[N_ * D_];
__device__ float g_z[N_ * D_];
__device__ float g_znpart[4][N_];
__device__ float g_edge_part[8][512 * D_];
__device__ int   g_cntp[8][512];
__device__ float g_etmp[512 * D_];
__device__ float g_hedges[512 * D_];
__device__ float g_hnpart[4][512];
__device__ float g_logits[512 * 512];
__device__ float g_sim[MHN_ * MHN_];
__device__ float g_attdot[MHN_ * MHN_];
__device__ float g_attm[MHN_ * NSPL_], g_atts[MHN_ * NSPL_];
__device__ float g_att[MHN_ * MHN_];
__device__ float g_lsem[MFN_ * NSPL_], g_lses[MFN_ * NSPL_];
__device__ float g_lse[MFN_];
__device__ float g_clrow[ECAP_];
__device__ float g_fnrow[MFN_], g_fncnt[MFN_];
__device__ float g_hnsum[MHN_], g_hncnt[MHN_];
__device__ int   g_nza[2048], g_nzb[2048];
__device__ float g_topo[SAMP_ * 2];

// ---------------- helpers ----------------
__device__ __forceinline__ float warp_sum(float v) {
#pragma unroll
    for (int o = 16; o > 0; o >>= 1) v += __shfl_xor_sync(0xffffffffu, v, o);
    return v;
}
__device__ __forceinline__ float warp_max(float v) {
#pragma unroll
    for (int o = 16; o > 0; o >>= 1) v = fmaxf(v, __shfl_xor_sync(0xffffffffu, v, o));
    return v;
}
__device__ __forceinline__ int warp_sum_i(int v) {
#pragma unroll
    for (int o = 16; o > 0; o >>= 1) v += __shfl_xor_sync(0xffffffffu, v, o);
    return v;
}
__device__ float block_sum(float v, float* sm) {
    int w = threadIdx.x >> 5, lane = threadIdx.x & 31, nw = blockDim.x >> 5;
    v = warp_sum(v);
    if (lane == 0) sm[w] = v;
    __syncthreads();
    float r = (threadIdx.x < nw) ? sm[threadIdx.x] : 0.f;
    if (w == 0) r = warp_sum(r);
    if (threadIdx.x == 0) sm[0] = r;
    __syncthreads();
    r = sm[0];
    __syncthreads();
    return r;
}
__device__ float block_max(float v, float* sm) {
    int w = threadIdx.x >> 5, lane = threadIdx.x & 31, nw = blockDim.x >> 5;
    v = warp_max(v);
    if (lane == 0) sm[w] = v;
    __syncthreads();
    float r = (threadIdx.x < nw) ? sm[threadIdx.x] : -FLT_MAX;
    if (w == 0) r = warp_max(r);
    if (threadIdx.x == 0) sm[0] = r;
    __syncthreads();
    r = sm[0];
    __syncthreads();
    return r;
}
__device__ __forceinline__ uint32_t f2tf32(float x) {
    uint32_t r;
    asm("cvt.rna.tf32.f32 %0, %1;" : "=r"(r) : "f"(x));
    return r;
}
__device__ __forceinline__ void mma_tf32(float* c, const uint32_t* a, const uint32_t* b) {
    asm volatile(
        "mma.sync.aligned.m16n8k8.row.col.f32.tf32.tf32.f32 "
        "{%0,%1,%2,%3}, {%4,%5,%6,%7}, {%8,%9}, {%0,%1,%2,%3};"
        : "+f"(c[0]), "+f"(c[1]), "+f"(c[2]), "+f"(c[3])
        : "r"(a[0]), "r"(a[1]), "r"(a[2]), "r"(a[3]), "r"(b[0]), "r"(b[1]));
}
__device__ __forceinline__ void ldsm4(uint32_t* r, uint32_t addr) {
    asm volatile("ldmatrix.sync.aligned.m8n8.x4.shared.b16 {%0,%1,%2,%3}, [%4];"
                 : "=r"(r[0]), "=r"(r[1]), "=r"(r[2]), "=r"(r[3]) : "r"(addr));
}
__device__ __forceinline__ uint32_t smem_u32(const void* p) {
    uint32_t a;
    asm("{ .reg .u64 t; cvta.to.shared.u64 t, %1; cvt.u32.u64 %0, t; }" : "=r"(a) : "l"(p));
    return a;
}
__device__ __forceinline__ void msmerge(float& m, float& s, float m2, float s2) {
    float M = fmaxf(m, m2);
    s = s * __expf(m - M) + s2 * __expf(m2 - M);
    m = M;
}
__device__ __forceinline__ void msadd(float& m, float& s, float v) {
    if (v <= m) s += __expf(v - m);
    else { s = s * __expf(m - v) + 1.f; m = v; }
}
__device__ __forceinline__ void split4(float4 v, uint32_t* hi, uint32_t* lo) {
    uint32_t h;
    h = f2tf32(v.x); hi[0] = h; lo[0] = f2tf32(v.x - __uint_as_float(h));
    h = f2tf32(v.y); hi[1] = h; lo[1] = f2tf32(v.y - __uint_as_float(h));
    h = f2tf32(v.z); hi[2] = h; lo[2] = f2tf32(v.z - __uint_as_float(h));
    h = f2tf32(v.w); hi[3] = h; lo[3] = f2tf32(v.w - __uint_as_float(h));
}

// ---------------- kernels (identical to R11 best) ----------------

__global__ void count_nz_kernel(const float4* __restrict__ a, const float4* __restrict__ b) {
    const int n4 = N_ * E_ / 4;
    int ca = 0, cb = 0;
    for (int i = blockIdx.x * blockDim.x + threadIdx.x; i < n4; i += gridDim.x * blockDim.x) {
        float4 x = a[i];
        ca += (x.x != 0.f) + (x.y != 0.f) + (x.z != 0.f) + (x.w != 0.f);
        float4 y = b[i];
        cb += (y.x != 0.f) + (y.y != 0.f) + (y.z != 0.f) + (y.w != 0.f);
    }
    __shared__ int sa[32], sb[32];
    int w = threadIdx.x >> 5, lane = threadIdx.x & 31;
    ca = warp_sum_i(ca); cb = warp_sum_i(cb);
    if (lane == 0) { sa[w] = ca; sb[w] = cb; }
    __syncthreads();
    if (w == 0) {
        int x = (lane < 8) ? sa[lane] : 0;
        int y = (lane < 8) ? sb[lane] : 0;
        x = warp_sum_i(x); y = warp_sum_i(y);
        if (lane == 0) { g_nza[blockIdx.x] = x; g_nzb[blockIdx.x] = y; }
    }
}

__global__ void topo_kernel(const float* __restrict__ Ho, const float* __restrict__ Hp) {
    __shared__ float hoi[128], hpi[128];
    __shared__ float sm[32];
    int i = blockIdx.x;
    int tid = threadIdx.x;
    if (tid < SAMP_) { hoi[tid] = Ho[i * E_ + tid]; hpi[tid] = Hp[i * E_ + tid]; }
    else             { hoi[tid] = 0.f; hpi[tid] = 0.f; }
    __syncthreads();
    int w = tid >> 5, lane = tid & 31;
    float dn2 = 0.f, on2 = 0.f;
    for (int j = w; j < SAMP_; j += 4) {
        float as = 0.f, aps = 0.f;
#pragma unroll
        for (int t = 0; t < 4; t++) {
            int k = lane + 32 * t;
            if (k < SAMP_) {
                as  += hoi[k] * Ho[j * E_ + k];
                aps += hpi[k] * Hp[j * E_ + k];
            }
        }
        as = warp_sum(as);
        aps = warp_sum(aps);
        if (lane == 0) {
            float d = as - aps;
            dn2 += d * d;
            on2 += as * as;
        }
    }
    float D2 = block_sum(dn2, sm);
    float O2 = block_sum(on2, sm);
    if (tid == 0) { g_topo[i * 2] = D2; g_topo[i * 2 + 1] = O2; }
}

// TF32 MLP GEMM with ldmatrix fragment loads (split at smem-load).
template <bool RELU, bool NORM>
__global__ void gemm_tf32_kernel(const float* __restrict__ A, const float* __restrict__ B,
                                 const float* __restrict__ bias, float* __restrict__ C) {
    __shared__ uint32_t Ah[128][20], Al[128][20];
    __shared__ uint32_t Bnh[64][20], Bnl[64][20];
    __shared__ float ssq[128][9];
    const int bm = blockIdx.x * 128, bn = blockIdx.y * 64;
    const int tid = threadIdx.x;
    const int lane = tid & 31, wid = tid >> 5;
    const int wm = wid >> 1, wn = wid & 1;
    const int g = lane >> 2, t = lane & 3;
    const uint32_t aH = smem_u32(&Ah[0][0]), aL = smem_u32(&Al[0][0]);
    const uint32_t bH = smem_u32(&Bnh[0][0]), bL = smem_u32(&Bnl[0][0]);
    float acc[2][4][4];
#pragma unroll
    for (int m = 0; m < 2; m++)
#pragma unroll
        for (int n = 0; n < 4; n++)
#pragma unroll
            for (int q = 0; q < 4; q++) acc[m][n][q] = 0.f;

    const int arow = (lane & 7) + ((lane >> 3) & 1) * 8;
    const int acol = ((lane >> 4) & 1) * 4;
    const int brow = (lane & 7) + ((lane >> 4) & 1) * 8;
    const int bcol = ((lane >> 3) & 1) * 4;

    for (int k0 = 0; k0 < D_; k0 += 16) {
#pragma unroll
        for (int l = 0; l < 2; l++) {
            int id = tid * 2 + l;
            int r = id >> 2, c4 = id & 3;
            float4 v = *(const float4*)&A[(bm + r) * D_ + k0 + c4 * 4];
            uint32_t hi[4], lo[4];
            split4(v, hi, lo);
            *(uint4*)&Ah[r][c4 * 4] = *(uint4*)hi;
            *(uint4*)&Al[r][c4 * 4] = *(uint4*)lo;
        }
        {
            int r = tid >> 4, c4 = tid & 15;
            float4 v = *(const float4*)&B[(k0 + r) * D_ + bn + c4 * 4];
            uint32_t hi[4], lo[4];
            split4(v, hi, lo);
#pragma unroll
            for (int j = 0; j < 4; j++) { Bnh[c4 * 4 + j][r] = hi[j]; Bnl[c4 * 4 + j][r] = lo[j]; }
        }
        __syncthreads();
#pragma unroll
        for (int ks = 0; ks < 16; ks += 8) {
            uint32_t ah[2][4], al[2][4], bh[2][4], bl[2][4];
#pragma unroll
            for (int m = 0; m < 2; m++) {
                uint32_t off = ((wm * 32 + m * 16 + arow) * 20 + ks + acol) * 4;
                ldsm4(ah[m], aH + off);
                ldsm4(al[m], aL + off);
            }
#pragma unroll
            for (int np = 0; np < 2; np++) {
                uint32_t off = ((wn * 32 + np * 16 + brow) * 20 + ks + bcol) * 4;
                ldsm4(bh[np], bH + off);
                ldsm4(bl[np], bL + off);
            }
#pragma unroll
            for (int m = 0; m < 2; m++)
#pragma unroll
                for (int n = 0; n < 4; n++) {
                    uint32_t* bhp = &bh[n >> 1][(n & 1) * 2];
                    uint32_t* blp = &bl[n >> 1][(n & 1) * 2];
                    mma_tf32(acc[m][n], ah[m], bhp);
                    mma_tf32(acc[m][n], ah[m], blp);
                    mma_tf32(acc[m][n], al[m], bhp);
                }
        }
        __syncthreads();
    }
    float sq[2][2] = {};
#pragma unroll
    for (int m = 0; m < 2; m++) {
        int row0 = bm + wm * 32 + m * 16 + g;
        int row1 = row0 + 8;
#pragma unroll
        for (int n = 0; n < 4; n++) {
            int col = bn + wn * 32 + n * 8 + t * 2;
            float b0 = bias[col], b1 = bias[col + 1];
            float v00 = acc[m][n][0] + b0, v01 = acc[m][n][1] + b1;
            float v10 = acc[m][n][2] + b0, v11 = acc[m][n][3] + b1;
            if (RELU) {
                v00 = fmaxf(v00, 0.f); v01 = fmaxf(v01, 0.f);
                v10 = fmaxf(v10, 0.f); v11 = fmaxf(v11, 0.f);
            }
            *(float2*)&C[row0 * D_ + col] = make_float2(v00, v01);
            *(float2*)&C[row1 * D_ + col] = make_float2(v10, v11);
            if (NORM) {
                sq[m][0] += v00 * v00 + v01 * v01;
                sq[m][1] += v10 * v10 + v11 * v11;
            }
        }
    }
    if (NORM) {
#pragma unroll
        for (int m = 0; m < 2; m++) {
            ssq[wm * 32 + m * 16 + g][wn * 4 + t] = sq[m][0];
            ssq[wm * 32 + m * 16 + g + 8][wn * 4 + t] = sq[m][1];
        }
        __syncthreads();
        if (tid < 128) {
            float s = 0.f;
#pragma unroll
            for (int q = 0; q < 8; q++) s += ssq[tid][q];
            g_znpart[blockIdx.y][bm + tid] = s;
        }
    }
}

// TF32 att/sim/lse GEMM with ldmatrix, inline norms.
__global__ void attgemm_kernel() {
    __shared__ uint32_t Ah[64][20], Al[64][20];
    __shared__ uint32_t Bnh[128][20], Bnl[128][20];
    __shared__ float redm[64][2], reds[64][2];
    __shared__ float redm2[64][2], reds2[64][2];
    __shared__ float s_invi[64], s_invj[128];
    const int bm = blockIdx.x * 64;
    const int sp = blockIdx.y;
    const int j0 = sp * 128;
    const int tid = threadIdx.x;
    const int lane = tid & 31, wid = tid >> 5;
    const int wm = wid >> 1, wn = wid & 1;
    const int g = lane >> 2, t = lane & 3;
    const uint32_t aH = smem_u32(&Ah[0][0]), aL = smem_u32(&Al[0][0]);
    const uint32_t bH = smem_u32(&Bnh[0][0]), bL = smem_u32(&Bnl[0][0]);
    if (tid < 64) {
        int r = bm + tid;
        float s = g_znpart[0][r] + g_znpart[1][r] + g_znpart[2][r] + g_znpart[3][r];
        s_invi[tid] = 1.f / fmaxf(sqrtf(s), 1e-8f);
    } else if (tid >= 128) {
        int j = tid - 128;
        int r = j0 + j;
        float s = g_znpart[0][r] + g_znpart[1][r] + g_znpart[2][r] + g_znpart[3][r];
        s_invj[j] = 1.f / fmaxf(sqrtf(s), 1e-8f);
    }
    float acc[8][4];
#pragma unroll
    for (int n = 0; n < 8; n++)
#pragma unroll
        for (int q = 0; q < 4; q++) acc[n][q] = 0.f;

    const int arow = (lane & 7) + ((lane >> 3) & 1) * 8;
    const int acol = ((lane >> 4) & 1) * 4;
    const int brow = (lane & 7) + ((lane >> 4) & 1) * 8;
    const int bcol = ((lane >> 3) & 1) * 4;

    for (int k0 = 0; k0 < D_; k0 += 16) {
        {
            int r = tid >> 2, c4 = tid & 3;
            float4 v = *(const float4*)&g_z[(bm + r) * D_ + k0 + c4 * 4];
            uint32_t hi[4], lo[4];
            split4(v, hi, lo);
            *(uint4*)&Ah[r][c4 * 4] = *(uint4*)hi;
            *(uint4*)&Al[r][c4 * 4] = *(uint4*)lo;
        }
#pragma unroll
        for (int l = 0; l < 2; l++) {
            int id = tid + 256 * l;
            int jr = id >> 2, c4 = id & 3;
            float4 v = *(const float4*)&g_z[(j0 + jr) * D_ + k0 + c4 * 4];
            uint32_t hi[4], lo[4];
            split4(v, hi, lo);
            *(uint4*)&Bnh[jr][c4 * 4] = *(uint4*)hi;
            *(uint4*)&Bnl[jr][c4 * 4] = *(uint4*)lo;
        }
        __syncthreads();
#pragma unroll
        for (int ks = 0; ks < 16; ks += 8) {
            uint32_t ah[4], al[4];
            {
                uint32_t off = ((wm * 16 + arow) * 20 + ks + acol) * 4;
                ldsm4(ah, aH + off);
                ldsm4(al, aL + off);
            }
#pragma unroll
            for (int np = 0; np < 4; np++) {
                uint32_t b4h[4], b4l[4];
                uint32_t off = ((wn * 64 + np * 16 + brow) * 20 + ks + bcol) * 4;
                ldsm4(b4h, bH + off);
                ldsm4(b4l, bL + off);
                mma_tf32(acc[2 * np],     ah, b4h);
                mma_tf32(acc[2 * np],     ah, b4l);
                mma_tf32(acc[2 * np],     al, b4h);
                mma_tf32(acc[2 * np + 1], ah, b4h + 2);
                mma_tf32(acc[2 * np + 1], ah, b4l + 2);
                mma_tf32(acc[2 * np + 1], al, b4h + 2);
            }
        }
        __syncthreads();
    }
    const int rbase = wm * 16 + g;
    const int r0 = bm + rbase, r1 = r0 + 8;
    if (j0 < MHN_) {
        float i0v = s_invi[rbase], i1v = s_invi[rbase + 8];
#pragma unroll
        for (int n = 0; n < 8; n++) {
            int cl = wn * 64 + n * 8 + 2 * t;
            int j = j0 + cl;
            if (j < MHN_) {
                float jv = s_invj[cl];
                if (r0 < MHN_) { g_attdot[r0 * MHN_ + j] = acc[n][0]; g_sim[r0 * MHN_ + j] = acc[n][0] * i0v * jv; }
                if (r1 < MHN_) { g_attdot[r1 * MHN_ + j] = acc[n][2]; g_sim[r1 * MHN_ + j] = acc[n][2] * i1v * jv; }
            }
            if (j + 1 < MHN_) {
                float jv = s_invj[cl + 1];
                if (r0 < MHN_) { g_attdot[r0 * MHN_ + j + 1] = acc[n][1]; g_sim[r0 * MHN_ + j + 1] = acc[n][1] * i0v * jv; }
                if (r1 < MHN_) { g_attdot[r1 * MHN_ + j + 1] = acc[n][3]; g_sim[r1 * MHN_ + j + 1] = acc[n][3] * i1v * jv; }
            }
        }
    }
    {
        float m0 = -FLT_MAX, m1 = -FLT_MAX;
#pragma unroll
        for (int n = 0; n < 8; n++) {
            m0 = fmaxf(m0, fmaxf(acc[n][0], acc[n][1]));
            m1 = fmaxf(m1, fmaxf(acc[n][2], acc[n][3]));
        }
        float s0 = 0.f, s1 = 0.f;
#pragma unroll
        for (int n = 0; n < 8; n++) {
            s0 += __expf(acc[n][0] - m0) + __expf(acc[n][1] - m0);
            s1 += __expf(acc[n][2] - m1) + __expf(acc[n][3] - m1);
        }
#pragma unroll
        for (int o = 1; o <= 2; o <<= 1) {
            float mo = __shfl_xor_sync(0xffffffffu, m0, o);
            float so = __shfl_xor_sync(0xffffffffu, s0, o);
            msmerge(m0, s0, mo, so);
            mo = __shfl_xor_sync(0xffffffffu, m1, o);
            so = __shfl_xor_sync(0xffffffffu, s1, o);
            msmerge(m1, s1, mo, so);
        }
        if (t == 0) {
            redm[rbase][wn] = m0; reds[rbase][wn] = s0;
            redm[rbase + 8][wn] = m1; reds[rbase + 8][wn] = s1;
        }
    }
    if (bm < MFN_) {
        float vt0 = s_invi[rbase] * (1.f / TAU_F);
        float vt1 = s_invi[rbase + 8] * (1.f / TAU_F);
        float m2 = -FLT_MAX, s2 = 0.f, m3 = -FLT_MAX, s3 = 0.f;
#pragma unroll
        for (int n = 0; n < 8; n++) {
            int cl = wn * 64 + n * 8 + 2 * t;
            float j0v = s_invj[cl], j1v = s_invj[cl + 1];
            msadd(m2, s2, acc[n][0] * vt0 * j0v);
            msadd(m2, s2, acc[n][1] * vt0 * j1v);
            msadd(m3, s3, acc[n][2] * vt1 * j0v);
            msadd(m3, s3, acc[n][3] * vt1 * j1v);
        }
#pragma unroll
        for (int o = 1; o <= 2; o <<= 1) {
            float mo = __shfl_xor_sync(0xffffffffu, m2, o);
            float so = __shfl_xor_sync(0xffffffffu, s2, o);
            msmerge(m2, s2, mo, so);
            mo = __shfl_xor_sync(0xffffffffu, m3, o);
            so = __shfl_xor_sync(0xffffffffu, s3, o);
            msmerge(m3, s3, mo, so);
        }
        if (t == 0) {
            redm2[rbase][wn] = m2; reds2[rbase][wn] = s2;
            redm2[rbase + 8][wn] = m3; reds2[rbase + 8][wn] = s3;
        }
    }
    __syncthreads();
    if (tid < 64) {
        int i = bm + tid;
        if (i < MHN_) {
            float M = redm[tid][0], S = reds[tid][0];
            msmerge(M, S, redm[tid][1], reds[tid][1]);
            g_attm[i * NSPL_ + sp] = M;
            g_atts[i * NSPL_ + sp] = S;
        }
        if (i < MFN_) {
            float M = redm2[tid][0], S = reds2[tid][0];
            msmerge(M, S, redm2[tid][1], reds2[tid][1]);
            g_lsem[i * NSPL_ + sp] = M;
            g_lses[i * NSPL_ + sp] = S;
        }
    }
}

// cl logits GEMM, inline norms
__global__ void clgemm_kernel() {
    __shared__ float As[16][68];
    __shared__ float Bs[16][132];
    __shared__ float s_invi[64], s_invj[128];
    const int bm = blockIdx.x * 64;
    const int j0 = blockIdx.y * 128;
    const int tid = threadIdx.x;
    const int tx = tid & 15, ty = tid >> 4;
    if (tid < 64) {
        int r = bm + tid;
        float s = g_znpart[0][r] + g_znpart[1][r] + g_znpart[2][r] + g_znpart[3][r];
        s_invi[tid] = 1.f / fmaxf(sqrtf(s), 1e-8f);
    }
    {
        int r = j0 + tid;
        float s = g_hnpart[0][r] + g_hnpart[1][r] + g_hnpart[2][r] + g_hnpart[3][r];
        s_invj[tid] = 1.f / fmaxf(sqrtf(s), 1e-8f);
    }
    float acc[8][8];
#pragma unroll
    for (int r = 0; r < 8; r++)
#pragma unroll
        for (int c = 0; c < 8; c++) acc[r][c] = 0.f;
    for (int k0 = 0; k0 < D_; k0 += 16) {
#pragma unroll
        for (int l = 0; l < 2; l++) {
            int id = tid * 2 + l;
            int r = id >> 2, c4 = id & 3;
            float4 v = *(const float4*)&g_z[(bm + r) * D_ + k0 + c4 * 4];
            As[c4 * 4 + 0][r] = v.x;
            As[c4 * 4 + 1][r] = v.y;
            As[c4 * 4 + 2][r] = v.z;
            As[c4 * 4 + 3][r] = v.w;
        }
#pragma unroll
        for (int l = 0; l < 4; l++) {
            int id = tid + 128 * l;
            int jr = id >> 2, c4 = id & 3;
            float4 v = *(const float4*)&g_hedges[(j0 + jr) * D_ + k0 + c4 * 4];
            Bs[c4 * 4 + 0][jr] = v.x;
            Bs[c4 * 4 + 1][jr] = v.y;
            Bs[c4 * 4 + 2][jr] = v.z;
            Bs[c4 * 4 + 3][jr] = v.w;
        }
        __syncthreads();
#pragma unroll
        for (int kk = 0; kk < 16; kk++) {
            float4 a0 = *(const float4*)&As[kk][ty * 8];
            float4 a1 = *(const float4*)&As[kk][ty * 8 + 4];
            float4 b0 = *(const float4*)&Bs[kk][tx * 8];
            float4 b1 = *(const float4*)&Bs[kk][tx * 8 + 4];
            float a[8] = {a0.x, a0.y, a0.z, a0.w, a1.x, a1.y, a1.z, a1.w};
            float b[8] = {b0.x, b0.y, b0.z, b0.w, b1.x, b1.y, b1.z, b1.w};
#pragma unroll
            for (int r = 0; r < 8; r++)
#pragma unroll
                for (int c = 0; c < 8; c++) acc[r][c] += a[r] * b[c];
        }
        __syncthreads();
    }
#pragma unroll
    for (int r = 0; r < 8; r++) {
        int i = bm + ty * 8 + r;
        if (i >= ECAP_) continue;
        float vi = s_invi[ty * 8 + r] * (1.f / TAU_F);
#pragma unroll
        for (int c = 0; c < 8; c += 2) {
            int j = j0 + tx * 8 + c;
            if (j < ECAP_ - 1) {
                *(float2*)&g_logits[i * 512 + j] =
                    make_float2(acc[r][c] * vi * s_invj[tx * 8 + c],
                                acc[r][c + 1] * vi * s_invj[tx * 8 + c + 1]);
            } else {
                if (j < ECAP_) g_logits[i * 512 + j] = acc[r][c] * vi * s_invj[tx * 8 + c];
                if (j + 1 < ECAP_) g_logits[i * 512 + j + 1] = acc[r][c + 1] * vi * s_invj[tx * 8 + c + 1];
            }
        }
    }
}

// Sparse edge aggregation
__global__ void edge_part_kernel(const float* __restrict__ Hp, const float* __restrict__ z) {
    __shared__ float racc[8][4][256];
    __shared__ int rcnt[8][4];
    const int tid = threadIdx.x;
    const int lane = tid & 31, w = tid >> 5;
    const int e0 = blockIdx.x * 4, sp = blockIdx.y;
    float acc[4][8] = {};
    int cnt[4] = {0, 0, 0, 0};
    const int ibase = sp * 1024;
#pragma unroll 1
    for (int ic = 0; ic < 1024; ic += 256) {
        int i0 = ibase + ic;
        float4 v = *(const float4*)&Hp[(size_t)(i0 + tid) * E_ + e0];
        int m = (v.x > 0.f) | ((v.y > 0.f) << 1) | ((v.z > 0.f) << 2) | ((v.w > 0.f) << 3);
        unsigned b = __ballot_sync(0xffffffffu, m != 0);
        int rowbase = i0 + w * 32;
        while (b) {
            int src = __ffs(b) - 1;
            b &= b - 1;
            int mm = __shfl_sync(0xffffffffu, m, src);
            const float* zr = &z[(size_t)(rowbase + src) * D_];
            float zv[8];
#pragma unroll
            for (int t = 0; t < 8; t++) zv[t] = zr[lane + 32 * t];
            switch (mm) {
                case 1:
#pragma unroll
                    for (int t = 0; t < 8; t++) acc[0][t] += zv[t];
                    cnt[0]++; break;
                case 2:
#pragma unroll
                    for (int t = 0; t < 8; t++) acc[1][t] += zv[t];
                    cnt[1]++; break;
                case 4:
#pragma unroll
                    for (int t = 0; t < 8; t++) acc[2][t] += zv[t];
                    cnt[2]++; break;
                case 8:
#pragma unroll
                    for (int t = 0; t < 8; t++) acc[3][t] += zv[t];
                    cnt[3]++; break;
                default:
                    if (mm & 1) {
#pragma unroll
                        for (int t = 0; t < 8; t++) acc[0][t] += zv[t];
                        cnt[0]++;
                    }
                    if (mm & 2) {
#pragma unroll
                        for (int t = 0; t < 8; t++) acc[1][t] += zv[t];
                        cnt[1]++;
                    }
                    if (mm & 4) {
#pragma unroll
                        for (int t = 0; t < 8; t++) acc[2][t] += zv[t];
                        cnt[2]++;
                    }
                    if (mm & 8) {
#pragma unroll
                        for (int t = 0; t < 8; t++) acc[3][t] += zv[t];
                        cnt[3]++;
                    }
            }
        }
    }
#pragma unroll
    for (int e = 0; e < 4; e++)
#pragma unroll
        for (int t = 0; t < 8; t++) racc[w][e][lane + 32 * t] = acc[e][t];
    if (lane == 0) {
#pragma unroll
        for (int e = 0; e < 4; e++) rcnt[w][e] = cnt[e];
    }
    __syncthreads();
#pragma unroll
    for (int e = 0; e < 4; e++) {
        float s = 0.f;
#pragma unroll
        for (int q = 0; q < 8; q++) s += racc[q][e][tid];
        g_edge_part[sp][(e0 + e) * D_ + tid] = s;
    }
    if (tid < 4) {
        int c = 0;
#pragma unroll
        for (int q = 0; q < 8; q++) c += rcnt[q][tid];
        g_cntp[sp][e0 + tid] = c;
    }
}

// edge MLP layer 1 (mean fused)
__global__ void gemm64_e1_kernel(const float* __restrict__ B, const float* __restrict__ bias,
                                 float* __restrict__ C) {
    __shared__ float As[16][68];
    __shared__ float Bs[16][68];
    const int bm = blockIdx.x * 64, bn = blockIdx.y * 64;
    const int tid = threadIdx.x;
    const int tx = tid & 15, ty = tid >> 4;
    const int arow = bm + (tid >> 2);
    float cinv = 0.f;
    {
        int c = 0;
#pragma unroll
        for (int p = 0; p < 8; p++) c += g_cntp[p][arow];
        cinv = (c > 0 && arow < ECAP_) ? 1.f / (float)c : 0.f;
    }
    float acc[4][4] = {};
    for (int k0 = 0; k0 < D_; k0 += 16) {
        {
            int r = tid >> 2, c4 = tid & 3;
            float4 s = make_float4(0.f, 0.f, 0.f, 0.f);
#pragma unroll
            for (int p = 0; p < 8; p++) {
                float4 t = *(const float4*)&g_edge_part[p][arow * D_ + k0 + c4 * 4];
                s.x += t.x; s.y += t.y; s.z += t.z; s.w += t.w;
            }
            As[c4 * 4 + 0][r] = s.x * cinv;
            As[c4 * 4 + 1][r] = s.y * cinv;
            As[c4 * 4 + 2][r] = s.z * cinv;
            As[c4 * 4 + 3][r] = s.w * cinv;
        }
        {
            int r = tid >> 4, c4 = tid & 15;
            float4 v = *(const float4*)&B[(k0 + r) * D_ + bn + c4 * 4];
            *(float4*)&Bs[r][c4 * 4] = v;
        }
        __syncthreads();
#pragma unroll
        for (int kk = 0; kk < 16; kk++) {
            float a[4], b[4];
#pragma unroll
            for (int u = 0; u < 4; u++) a[u] = As[kk][ty * 4 + u];
#pragma unroll
            for (int u = 0; u < 4; u++) b[u] = Bs[kk][tx * 4 + u];
#pragma unroll
            for (int i = 0; i < 4; i++)
#pragma unroll
                for (int j = 0; j < 4; j++) acc[i][j] += a[i] * b[j];
        }
        __syncthreads();
    }
#pragma unroll
    for (int i = 0; i < 4; i++) {
        int row = bm + ty * 4 + i;
#pragma unroll
        for (int j = 0; j < 4; j++) {
            int col = bn + tx * 4 + j;
            C[row * D_ + col] = fmaxf(acc[i][j] + bias[col], 0.f);
        }
    }
}

// edge MLP layer 2 (hnorm partials fused)
__global__ void gemm64_e2_kernel(const float* __restrict__ A, const float* __restrict__ B,
                                 const float* __restrict__ bias, float* __restrict__ C) {
    __shared__ float As[16][68];
    __shared__ float Bs[16][68];
    __shared__ float ssq[64][17];
    const int bm = blockIdx.x * 64, bn = blockIdx.y * 64;
    const int tid = threadIdx.x;
    const int tx = tid & 15, ty = tid >> 4;
    float acc[4][4] = {};
    for (int k0 = 0; k0 < D_; k0 += 16) {
        {
            int r = tid >> 2, c4 = tid & 3;
            float4 v = *(const float4*)&A[(bm + r) * D_ + k0 + c4 * 4];
            As[c4 * 4 + 0][r] = v.x;
            As[c4 * 4 + 1][r] = v.y;
            As[c4 * 4 + 2][r] = v.z;
            As[c4 * 4 + 3][r] = v.w;
        }
        {
            int r = tid >> 4, c4 = tid & 15;
            float4 v = *(const float4*)&B[(k0 + r) * D_ + bn + c4 * 4];
            *(float4*)&Bs[r][c4 * 4] = v;
        }
        __syncthreads();
#pragma unroll
        for (int kk = 0; kk < 16; kk++) {
            float a[4], b[4];
#pragma unroll
            for (int u = 0; u < 4; u++) a[u] = As[kk][ty * 4 + u];
#pragma unroll
            for (int u = 0; u < 4; u++) b[u] = Bs[kk][tx * 4 + u];
#pragma unroll
            for (int i = 0; i < 4; i++)
#pragma unroll
                for (int j = 0; j < 4; j++) acc[i][j] += a[i] * b[j];
        }
        __syncthreads();
    }
#pragma unroll
    for (int i = 0; i < 4; i++) {
        int row = bm + ty * 4 + i;
        float sq = 0.f;
#pragma unroll
        for (int j = 0; j < 4; j++) {
            int col = bn + tx * 4 + j;
            float v = acc[i][j] + bias[col];
            C[row * D_ + col] = v;
            sq += v * v;
        }
        ssq[ty * 4 + i][tx] = sq;
    }
    __syncthreads();
    if (tid < 64) {
        float s = 0.f;
#pragma unroll
        for (int q = 0; q < 16; q++) s += ssq[tid][q];
        g_hnpart[blockIdx.y][bm + tid] = s;
    }
}

// merged finalize: att rows (0..199), lse (200)
__global__ void merge_kernel() {
    int b = blockIdx.x;
    if (b < MHN_) {
        int i = b;
        __shared__ float Ms, Ss;
        if (threadIdx.x == 0) {
            float M = -FLT_MAX;
            for (int p = 0; p < NSPL_; p++) M = fmaxf(M, g_attm[i * NSPL_ + p]);
            float S = 0.f;
            for (int p = 0; p < NSPL_; p++) S += g_atts[i * NSPL_ + p] * __expf(g_attm[i * NSPL_ + p] - M);
            Ms = M; Ss = S;
        }
        __syncthreads();
        for (int j = threadIdx.x; j < MHN_; j += blockDim.x)
            g_att[i * MHN_ + j] = __expf(g_attdot[i * MHN_ + j] - Ms) / Ss;
    } else {
        int i = threadIdx.x;
        if (i < MFN_) {
            float M = -FLT_MAX;
            for (int p = 0; p < NSPL_; p++) M = fmaxf(M, g_lsem[i * NSPL_ + p]);
            float S = 0.f;
            for (int p = 0; p < NSPL_; p++) S += g_lses[i * NSPL_ + p] * __expf(g_lsem[i * NSPL_ + p] - M);
            g_lse[i] = M + logf(S);
        }
    }
}

// fused losses
__global__ void losses_kernel(const float* __restrict__ Ho, const float* __restrict__ Hp) {
    __shared__ float sm[32];
    int b = blockIdx.x;
    int tid = threadIdx.x;
    if (b < ECAP_) {
        int i = b;
        float lm = -FLT_MAX;
        for (int j = tid; j < ECAP_; j += 256) lm = fmaxf(lm, g_logits[i * 512 + j]);
        float M = block_max(lm, sm);
        float ls = 0.f;
        for (int j = tid; j < ECAP_; j += 256) ls += __expf(g_logits[i * 512 + j] - M);
        float S = block_sum(ls, sm);
        if (tid == 0) g_clrow[i] = g_logits[i * 512 + i] - (M + logf(S));
    } else {
        int i = b - ECAP_;
        {
            int j = tid;
            bool act = j < MHN_;
            float simv = act ? g_sim[i * MHN_ + j] : 0.f;
            float attv = act ? g_att[i * MHN_ + j] : 1.f;
            bool mask = act && (j != i) && (simv > MU_F) && (attv < NU_F);
            float neg = -simv / TAU_F;
            float m = block_max(mask ? neg : -FLT_MAX, sm);
            if (m == -FLT_MAX) {
                if (tid == 0) { g_hnsum[i] = 0.f; g_hncnt[i] = 0.f; }
            } else {
                float s = block_sum(mask ? expf(neg - m) : 0.f, sm);
                float lse = m + logf(s);
                float wgt = fminf(simv / MU_F, 1.f);
                float pair = -wgt * (neg - lse);
                float ps = block_sum(mask ? pair : 0.f, sm);
                float pc = block_sum(mask ? 1.f : 0.f, sm);
                if (tid == 0) { g_hnsum[i] = ps; g_hncnt[i] = pc; }
            }
        }
        if (i < MFN_) {
            __shared__ unsigned char cand[128];
            __shared__ short clist[MFN_];
            __shared__ int ncand;
            if (tid < 128) cand[tid] = 0;
            __syncthreads();
            if (tid < MFN_) {
                bool g = (tid > i) && (g_sim[i * MHN_ + tid] > GAMMA_F)
                                   && (g_att[i * MHN_ + tid] > DELTA_F);
                cand[tid] = g ? 1 : 0;
            }
            __syncthreads();
            if (tid == 0) {
                int n = 0;
                for (int j = i + 1; j < MFN_; j++) if (cand[j]) clist[n++] = (short)j;
                ncand = n;
            }
            __syncthreads();
            int nc = ncand;
            float fsum = 0.f, fcnt = 0.f;
            for (int k = 0; k < nc; k++) {
                int j = clist[k];
                float ao = 0.f, ap = 0.f;
                for (int t = tid; t < E_; t += 256) {
                    ao += Ho[i * E_ + t] * Ho[j * E_ + t];
                    ap += Hp[i * E_ + t] * Hp[j * E_ + t];
                }
                ao = block_sum(ao, sm);
                ap = block_sum(ap, sm);
                if (ap == 0.f && ao > 0.f) {
                    fsum += -(g_sim[i * MHN_ + j] / TAU_F - g_lse[i]);
                    fcnt += 1.f;
                }
            }
            if (tid == 0) { g_fnrow[i] = fsum; g_fncnt[i] = fcnt; }
        }
    }
}

// final combine
__global__ void final_kernel(const float* __restrict__ bw, float* __restrict__ out) {
    __shared__ float sm[32];
    int tid = threadIdx.x;
    float v = 0.f;
    for (int i = tid; i < ECAP_; i += 512) v += g_clrow[i];
    float clsum = block_sum(v, sm);
    v = 0.f; float c = 0.f;
    for (int i = tid; i < MFN_; i += 512) { v += g_fnrow[i]; c += g_fncnt[i]; }
    float fnsum = block_sum(v, sm);
    float fncnt = block_sum(c, sm);
    v = 0.f; c = 0.f;
    for (int i = tid; i < MHN_; i += 512) { v += g_hnsum[i]; c += g_hncnt[i]; }
    float hnsum = block_sum(v, sm);
    float hncnt = block_sum(c, sm);
    float d2 = 0.f, o2 = 0.f;
    for (int i = tid; i < SAMP_; i += 512) { d2 += g_topo[i * 2]; o2 += g_topo[i * 2 + 1]; }
    float D2 = block_sum(d2, sm);
    float O2 = block_sum(o2, sm);
    float za = 0.f, zb = 0.f;
    for (int i = tid; i < 2048; i += 512) { za += (float)g_nza[i]; zb += (float)g_nzb[i]; }
    float NZ = block_sum(za, sm);
    float NZP = block_sum(zb, sm);
    if (tid == 0) {
        float cl_loss = -clsum / (float)ECAP_;
        float fn_loss = (fncnt > 0.f) ? fnsum / fmaxf(fncnt, 1.f) : 0.f;
        float hard_loss = (hncnt > 0.f) ? hnsum / fmaxf(hncnt, 1.f) : 0.f;
        float sparsity = (NZ > 0.f) ? NZP / fmaxf(NZ, 1.f) : 1.f;
        float dn = sqrtf(D2), on = sqrtf(O2);
        float topo = (on > 0.f) ? expf(-ALPHA_F * dn / fmaxf(on, 1e-12f)) : 1.f;
        float retention = sparsity * topo;
        out[0] = bw[0] * (retention * cl_loss + fn_loss + hard_loss);
    }
}

// ---------------- launch (fork/join streams) ----------------
extern "C" void kernel_launch(void* const* d_in, const int* in_sizes, int n_in,
                              void* d_out, int out_size) {
    (void)in_sizes; (void)n_in; (void)out_size;
    const float* Ho  = (const float*)d_in[0];
    const float* Hp  = (const float*)d_in[1];
    const float* ne  = (const float*)d_in[2];
    const float* bw  = (const float*)d_in[3];
    const float* Wn1 = (const float*)d_in[4];
    const float* bn1 = (const float*)d_in[5];
    const float* Wn2 = (const float*)d_in[6];
    const float* bn2 = (const float*)d_in[7];
    const float* We1 = (const float*)d_in[8];
    const float* be1 = (const float*)d_in[9];
    const float* We2 = (const float*)d_in[10];
    const float* be2 = (const float*)d_in[11];
    float* out = (float*)d_out;

    void *p;
    float *p_tmp, *p_z, *p_etmp, *p_hedges;
    cudaGetSymbolAddress(&p, g_tmp);    p_tmp    = (float*)p;
    cudaGetSymbolAddress(&p, g_z);      p_z      = (float*)p;
    cudaGetSymbolAddress(&p, g_etmp);   p_etmp   = (float*)p;
    cudaGetSymbolAddress(&p, g_hedges); p_hedges = (float*)p;

    // one-time creation of side streams/events (no device memory involved;
    // identical launch pattern on every call)
    static cudaStream_t s1, s2;
    static cudaEvent_t evRoot, evZ, evE, evC;
    static int inited = 0;
    if (!inited) {
        cudaStreamCreateWithFlags(&s1, cudaStreamNonBlocking);
        cudaStreamCreateWithFlags(&s2, cudaStreamNonBlocking);
        cudaEventCreateWithFlags(&evRoot, cudaEventDisableTiming);
        cudaEventCreateWithFlags(&evZ,   cudaEventDisableTiming);
        cudaEventCreateWithFlags(&evE,   cudaEventDisableTiming);
        cudaEventCreateWithFlags(&evC,   cudaEventDisableTiming);
        inited = 1;
    }

    // fork s2 at entry: independent H scans
    cudaEventRecord(evRoot, 0);
    cudaStreamWaitEvent(s2, evRoot, 0);
    count_nz_kernel<<<2048, 256, 0, s2>>>((const float4*)Ho, (const float4*)Hp);
    topo_kernel<<<SAMP_, 128, 0, s2>>>(Ho, Hp);
    cudaEventRecord(evC, s2);

    // main chain: node MLP
    gemm_tf32_kernel<true,  false><<<dim3(64, 4), 256>>>(ne,    Wn1, bn1, p_tmp);
    gemm_tf32_kernel<false, true ><<<dim3(64, 4), 256>>>(p_tmp, Wn2, bn2, p_z);

    // fork s1 after z: edge path
    cudaEventRecord(evZ, 0);
    cudaStreamWaitEvent(s1, evZ, 0);
    edge_part_kernel<<<dim3(ECAP_ / 4, 8), 256, 0, s1>>>(Hp, p_z);
    gemm64_e1_kernel<<<dim3(8, 4), 256, 0, s1>>>(We1, be1, p_etmp);
    gemm64_e2_kernel<<<dim3(8, 4), 256, 0, s1>>>(p_etmp, We2, be2, p_hedges);
    clgemm_kernel<<<dim3(8, 4), 128, 0, s1>>>();
    cudaEventRecord(evE, s1);

    // main chain continues: attention path
    attgemm_kernel<<<dim3(4, NSPL_), 256>>>();
    merge_kernel<<<MHN_ + 1, 256>>>();

    // join all branches, then losses + final
    cudaStreamWaitEvent(0, evE, 0);
    cudaStreamWaitEvent(0, evC, 0);
    losses_kernel<<<ECAP_ + MHN_, 256>>>(Ho, Hp);
    final_kernel<<<1, 512>>>(bw, out);
}

// round 15
// speedup vs baseline: 1.3199x; 1.0553x over previous
#include <cuda_runtime.h>
#include <math.h>
#include <cfloat>
#include <stdint.h>

// ---------------- constants ----------------
#define TAU_F   0.4f
#define ALPHA_F 1.0f
#define GAMMA_F 0.7f
#define DELTA_F 0.6f
#define MU_F    0.6f
#define NU_F    0.3f

#define N_  8192
#define E_  2048
#define D_  256
#define SAMP_ 100
#define MFN_  100
#define MHN_  200
#define ECAP_ 500
#define NSPL_ 64

// ---------------- scratch (device globals) ----------------
__device__ float g_tmp[N_ * D_];
__device__ float g_z[N_ * D_];
__device__ float g_znpart[4][N_];
__device__ float g_edge_part[8][512 * D_];
__device__ int   g_cntp[8][512];
__device__ float g_etmp[512 * D_];
__device__ float g_hedges[512 * D_];
__device__ float g_hnpart[4][512];
__device__ float g_logits[512 * 512];
__device__ float g_sim[MHN_ * MHN_];
__device__ float g_attdot[MHN_ * MHN_];
__device__ float g_attm[MHN_ * NSPL_], g_atts[MHN_ * NSPL_];
__device__ float g_att[MHN_ * MHN_];
__device__ float g_lsem[MFN_ * NSPL_], g_lses[MFN_ * NSPL_];
__device__ float g_lse[MFN_];
__device__ float g_clrow[ECAP_];
__device__ float g_fnrow[MFN_], g_fncnt[MFN_];
__device__ float g_hnsum[MHN_], g_hncnt[MHN_];
__device__ int   g_nza[2048], g_nzb[2048];
__device__ float g_topo[SAMP_ * 2];

// ---------------- helpers ----------------
__device__ __forceinline__ float warp_sum(float v) {
#pragma unroll
    for (int o = 16; o > 0; o >>= 1) v += __shfl_xor_sync(0xffffffffu, v, o);
    return v;
}
__device__ __forceinline__ float warp_max(float v) {
#pragma unroll
    for (int o = 16; o > 0; o >>= 1) v = fmaxf(v, __shfl_xor_sync(0xffffffffu, v, o));
    return v;
}
__device__ __forceinline__ int warp_sum_i(int v) {
#pragma unroll
    for (int o = 16; o > 0; o >>= 1) v += __shfl_xor_sync(0xffffffffu, v, o);
    return v;
}
__device__ float block_sum(float v, float* sm) {
    int w = threadIdx.x >> 5, lane = threadIdx.x & 31, nw = blockDim.x >> 5;
    v = warp_sum(v);
    if (lane == 0) sm[w] = v;
    __syncthreads();
    float r = (threadIdx.x < nw) ? sm[threadIdx.x] : 0.f;
    if (w == 0) r = warp_sum(r);
    if (threadIdx.x == 0) sm[0] = r;
    __syncthreads();
    r = sm[0];
    __syncthreads();
    return r;
}
__device__ float block_max(float v, float* sm) {
    int w = threadIdx.x >> 5, lane = threadIdx.x & 31, nw = blockDim.x >> 5;
    v = warp_max(v);
    if (lane == 0) sm[w] = v;
    __syncthreads();
    float r = (threadIdx.x < nw) ? sm[threadIdx.x] : -FLT_MAX;
    if (w == 0) r = warp_max(r);
    if (threadIdx.x == 0) sm[0] = r;
    __syncthreads();
    r = sm[0];
    __syncthreads();
    return r;
}
__device__ __forceinline__ uint32_t f2tf32(float x) {
    uint32_t r;
    asm("cvt.rna.tf32.f32 %0, %1;" : "=r"(r) : "f"(x));
    return r;
}
__device__ __forceinline__ void mma_tf32(float* c, const uint32_t* a, const uint32_t* b) {
    asm volatile(
        "mma.sync.aligned.m16n8k8.row.col.f32.tf32.tf32.f32 "
        "{%0,%1,%2,%3}, {%4,%5,%6,%7}, {%8,%9}, {%0,%1,%2,%3};"
        : "+f"(c[0]), "+f"(c[1]), "+f"(c[2]), "+f"(c[3])
        : "r"(a[0]), "r"(a[1]), "r"(a[2]), "r"(a[3]), "r"(b[0]), "r"(b[1]));
}
__device__ __forceinline__ void ldsm4(uint32_t* r, uint32_t addr) {
    asm volatile("ldmatrix.sync.aligned.m8n8.x4.shared.b16 {%0,%1,%2,%3}, [%4];"
                 : "=r"(r[0]), "=r"(r[1]), "=r"(r[2]), "=r"(r[3]) : "r"(addr));
}
__device__ __forceinline__ uint32_t smem_u32(const void* p) {
    uint32_t a;
    asm("{ .reg .u64 t; cvta.to.shared.u64 t, %1; cvt.u32.u64 %0, t; }" : "=r"(a) : "l"(p));
    return a;
}
__device__ __forceinline__ void msmerge(float& m, float& s, float m2, float s2) {
    float M = fmaxf(m, m2);
    s = s * __expf(m - M) + s2 * __expf(m2 - M);
    m = M;
}
__device__ __forceinline__ void msadd(float& m, float& s, float v) {
    if (v <= m) s += __expf(v - m);
    else { s = s * __expf(m - v) + 1.f; m = v; }
}
__device__ __forceinline__ void split4(float4 v, uint32_t* hi, uint32_t* lo) {
    uint32_t h;
    h = f2tf32(v.x); hi[0] = h; lo[0] = f2tf32(v.x - __uint_as_float(h));
    h = f2tf32(v.y); hi[1] = h; lo[1] = f2tf32(v.y - __uint_as_float(h));
    h = f2tf32(v.z); hi[2] = h; lo[2] = f2tf32(v.z - __uint_as_float(h));
    h = f2tf32(v.w); hi[3] = h; lo[3] = f2tf32(v.w - __uint_as_float(h));
}

// ---------------- kernels ----------------

__global__ void count_nz_kernel(const float4* __restrict__ a, const float4* __restrict__ b) {
    const int n4 = N_ * E_ / 4;
    int ca = 0, cb = 0;
    for (int i = blockIdx.x * blockDim.x + threadIdx.x; i < n4; i += gridDim.x * blockDim.x) {
        float4 x = a[i];
        ca += (x.x != 0.f) + (x.y != 0.f) + (x.z != 0.f) + (x.w != 0.f);
        float4 y = b[i];
        cb += (y.x != 0.f) + (y.y != 0.f) + (y.z != 0.f) + (y.w != 0.f);
    }
    __shared__ int sa[32], sb[32];
    int w = threadIdx.x >> 5, lane = threadIdx.x & 31;
    ca = warp_sum_i(ca); cb = warp_sum_i(cb);
    if (lane == 0) { sa[w] = ca; sb[w] = cb; }
    __syncthreads();
    if (w == 0) {
        int x = (lane < 8) ? sa[lane] : 0;
        int y = (lane < 8) ? sb[lane] : 0;
        x = warp_sum_i(x); y = warp_sum_i(y);
        if (lane == 0) { g_nza[blockIdx.x] = x; g_nzb[blockIdx.x] = y; }
    }
}

__global__ void topo_kernel(const float* __restrict__ Ho, const float* __restrict__ Hp) {
    __shared__ float hoi[128], hpi[128];
    __shared__ float sm[32];
    int i = blockIdx.x;
    int tid = threadIdx.x;
    if (tid < SAMP_) { hoi[tid] = Ho[i * E_ + tid]; hpi[tid] = Hp[i * E_ + tid]; }
    else             { hoi[tid] = 0.f; hpi[tid] = 0.f; }
    __syncthreads();
    int w = tid >> 5, lane = tid & 31;
    float dn2 = 0.f, on2 = 0.f;
    for (int j = w; j < SAMP_; j += 4) {
        float as = 0.f, aps = 0.f;
#pragma unroll
        for (int t = 0; t < 4; t++) {
            int k = lane + 32 * t;
            if (k < SAMP_) {
                as  += hoi[k] * Ho[j * E_ + k];
                aps += hpi[k] * Hp[j * E_ + k];
            }
        }
        as = warp_sum(as);
        aps = warp_sum(aps);
        if (lane == 0) {
            float d = as - aps;
            dn2 += d * d;
            on2 += as * as;
        }
    }
    float D2 = block_sum(dn2, sm);
    float O2 = block_sum(on2, sm);
    if (tid == 0) { g_topo[i * 2] = D2; g_topo[i * 2 + 1] = O2; }
}

// TF32 MLP GEMM with ldmatrix fragment loads (split at smem-load).
template <bool RELU, bool NORM>
__global__ void gemm_tf32_kernel(const float* __restrict__ A, const float* __restrict__ B,
                                 const float* __restrict__ bias, float* __restrict__ C) {
    __shared__ uint32_t Ah[128][20], Al[128][20];
    __shared__ uint32_t Bnh[64][20], Bnl[64][20];
    __shared__ float ssq[128][9];
    const int bm = blockIdx.x * 128, bn = blockIdx.y * 64;
    const int tid = threadIdx.x;
    const int lane = tid & 31, wid = tid >> 5;
    const int wm = wid >> 1, wn = wid & 1;
    const int g = lane >> 2, t = lane & 3;
    const uint32_t aH = smem_u32(&Ah[0][0]), aL = smem_u32(&Al[0][0]);
    const uint32_t bH = smem_u32(&Bnh[0][0]), bL = smem_u32(&Bnl[0][0]);
    float acc[2][4][4];
#pragma unroll
    for (int m = 0; m < 2; m++)
#pragma unroll
        for (int n = 0; n < 4; n++)
#pragma unroll
            for (int q = 0; q < 4; q++) acc[m][n][q] = 0.f;

    const int arow = (lane & 7) + ((lane >> 3) & 1) * 8;
    const int acol = ((lane >> 4) & 1) * 4;
    const int brow = (lane & 7) + ((lane >> 4) & 1) * 8;
    const int bcol = ((lane >> 3) & 1) * 4;

    for (int k0 = 0; k0 < D_; k0 += 16) {
#pragma unroll
        for (int l = 0; l < 2; l++) {
            int id = tid * 2 + l;
            int r = id >> 2, c4 = id & 3;
            float4 v = *(const float4*)&A[(bm + r) * D_ + k0 + c4 * 4];
            uint32_t hi[4], lo[4];
            split4(v, hi, lo);
            *(uint4*)&Ah[r][c4 * 4] = *(uint4*)hi;
            *(uint4*)&Al[r][c4 * 4] = *(uint4*)lo;
        }
        {
            int r = tid >> 4, c4 = tid & 15;
            float4 v = *(const float4*)&B[(k0 + r) * D_ + bn + c4 * 4];
            uint32_t hi[4], lo[4];
            split4(v, hi, lo);
#pragma unroll
            for (int j = 0; j < 4; j++) { Bnh[c4 * 4 + j][r] = hi[j]; Bnl[c4 * 4 + j][r] = lo[j]; }
        }
        __syncthreads();
#pragma unroll
        for (int ks = 0; ks < 16; ks += 8) {
            uint32_t ah[2][4], al[2][4], bh[2][4], bl[2][4];
#pragma unroll
            for (int m = 0; m < 2; m++) {
                uint32_t off = ((wm * 32 + m * 16 + arow) * 20 + ks + acol) * 4;
                ldsm4(ah[m], aH + off);
                ldsm4(al[m], aL + off);
            }
#pragma unroll
            for (int np = 0; np < 2; np++) {
                uint32_t off = ((wn * 32 + np * 16 + brow) * 20 + ks + bcol) * 4;
                ldsm4(bh[np], bH + off);
                ldsm4(bl[np], bL + off);
            }
#pragma unroll
            for (int m = 0; m < 2; m++)
#pragma unroll
                for (int n = 0; n < 4; n++) {
                    uint32_t* bhp = &bh[n >> 1][(n & 1) * 2];
                    uint32_t* blp = &bl[n >> 1][(n & 1) * 2];
                    mma_tf32(acc[m][n], ah[m], bhp);
                    mma_tf32(acc[m][n], ah[m], blp);
                    mma_tf32(acc[m][n], al[m], bhp);
                }
        }
        __syncthreads();
    }
    float sq[2][2] = {};
#pragma unroll
    for (int m = 0; m < 2; m++) {
        int row0 = bm + wm * 32 + m * 16 + g;
        int row1 = row0 + 8;
#pragma unroll
        for (int n = 0; n < 4; n++) {
            int col = bn + wn * 32 + n * 8 + t * 2;
            float b0 = bias[col], b1 = bias[col + 1];
            float v00 = acc[m][n][0] + b0, v01 = acc[m][n][1] + b1;
            float v10 = acc[m][n][2] + b0, v11 = acc[m][n][3] + b1;
            if (RELU) {
                v00 = fmaxf(v00, 0.f); v01 = fmaxf(v01, 0.f);
                v10 = fmaxf(v10, 0.f); v11 = fmaxf(v11, 0.f);
            }
            *(float2*)&C[row0 * D_ + col] = make_float2(v00, v01);
            *(float2*)&C[row1 * D_ + col] = make_float2(v10, v11);
            if (NORM) {
                sq[m][0] += v00 * v00 + v01 * v01;
                sq[m][1] += v10 * v10 + v11 * v11;
            }
        }
    }
    if (NORM) {
#pragma unroll
        for (int m = 0; m < 2; m++) {
            ssq[wm * 32 + m * 16 + g][wn * 4 + t] = sq[m][0];
            ssq[wm * 32 + m * 16 + g + 8][wn * 4 + t] = sq[m][1];
        }
        __syncthreads();
        if (tid < 128) {
            float s = 0.f;
#pragma unroll
            for (int q = 0; q < 8; q++) s += ssq[tid][q];
            g_znpart[blockIdx.y][bm + tid] = s;
        }
    }
}

// TF32 att/sim/lse GEMM with ldmatrix, inline norms.
__global__ void attgemm_kernel() {
    __shared__ uint32_t Ah[64][20], Al[64][20];
    __shared__ uint32_t Bnh[128][20], Bnl[128][20];
    __shared__ float redm[64][2], reds[64][2];
    __shared__ float redm2[64][2], reds2[64][2];
    __shared__ float s_invi[64], s_invj[128];
    const int bm = blockIdx.x * 64;
    const int sp = blockIdx.y;
    const int j0 = sp * 128;
    const int tid = threadIdx.x;
    const int lane = tid & 31, wid = tid >> 5;
    const int wm = wid >> 1, wn = wid & 1;
    const int g = lane >> 2, t = lane & 3;
    const uint32_t aH = smem_u32(&Ah[0][0]), aL = smem_u32(&Al[0][0]);
    const uint32_t bH = smem_u32(&Bnh[0][0]), bL = smem_u32(&Bnl[0][0]);
    if (tid < 64) {
        int r = bm + tid;
        float s = g_znpart[0][r] + g_znpart[1][r] + g_znpart[2][r] + g_znpart[3][r];
        s_invi[tid] = 1.f / fmaxf(sqrtf(s), 1e-8f);
    } else if (tid >= 128) {
        int j = tid - 128;
        int r = j0 + j;
        float s = g_znpart[0][r] + g_znpart[1][r] + g_znpart[2][r] + g_znpart[3][r];
        s_invj[j] = 1.f / fmaxf(sqrtf(s), 1e-8f);
    }
    float acc[8][4];
#pragma unroll
    for (int n = 0; n < 8; n++)
#pragma unroll
        for (int q = 0; q < 4; q++) acc[n][q] = 0.f;

    const int arow = (lane & 7) + ((lane >> 3) & 1) * 8;
    const int acol = ((lane >> 4) & 1) * 4;
    const int brow = (lane & 7) + ((lane >> 4) & 1) * 8;
    const int bcol = ((lane >> 3) & 1) * 4;

    for (int k0 = 0; k0 < D_; k0 += 16) {
        {
            int r = tid >> 2, c4 = tid & 3;
            float4 v = *(const float4*)&g_z[(bm + r) * D_ + k0 + c4 * 4];
            uint32_t hi[4], lo[4];
            split4(v, hi, lo);
            *(uint4*)&Ah[r][c4 * 4] = *(uint4*)hi;
            *(uint4*)&Al[r][c4 * 4] = *(uint4*)lo;
        }
#pragma unroll
        for (int l = 0; l < 2; l++) {
            int id = tid + 256 * l;
            int jr = id >> 2, c4 = id & 3;
            float4 v = *(const float4*)&g_z[(j0 + jr) * D_ + k0 + c4 * 4];
            uint32_t hi[4], lo[4];
            split4(v, hi, lo);
            *(uint4*)&Bnh[jr][c4 * 4] = *(uint4*)hi;
            *(uint4*)&Bnl[jr][c4 * 4] = *(uint4*)lo;
        }
        __syncthreads();
#pragma unroll
        for (int ks = 0; ks < 16; ks += 8) {
            uint32_t ah[4], al[4];
            {
                uint32_t off = ((wm * 16 + arow) * 20 + ks + acol) * 4;
                ldsm4(ah, aH + off);
                ldsm4(al, aL + off);
            }
#pragma unroll
            for (int np = 0; np < 4; np++) {
                uint32_t b4h[4], b4l[4];
                uint32_t off = ((wn * 64 + np * 16 + brow) * 20 + ks + bcol) * 4;
                ldsm4(b4h, bH + off);
                ldsm4(b4l, bL + off);
                mma_tf32(acc[2 * np],     ah, b4h);
                mma_tf32(acc[2 * np],     ah, b4l);
                mma_tf32(acc[2 * np],     al, b4h);
                mma_tf32(acc[2 * np + 1], ah, b4h + 2);
                mma_tf32(acc[2 * np + 1], ah, b4l + 2);
                mma_tf32(acc[2 * np + 1], al, b4h + 2);
            }
        }
        __syncthreads();
    }
    const int rbase = wm * 16 + g;
    const int r0 = bm + rbase, r1 = r0 + 8;
    if (j0 < MHN_) {
        float i0v = s_invi[rbase], i1v = s_invi[rbase + 8];
#pragma unroll
        for (int n = 0; n < 8; n++) {
            int cl = wn * 64 + n * 8 + 2 * t;
            int j = j0 + cl;
            if (j < MHN_) {
                float jv = s_invj[cl];
                if (r0 < MHN_) { g_attdot[r0 * MHN_ + j] = acc[n][0]; g_sim[r0 * MHN_ + j] = acc[n][0] * i0v * jv; }
                if (r1 < MHN_) { g_attdot[r1 * MHN_ + j] = acc[n][2]; g_sim[r1 * MHN_ + j] = acc[n][2] * i1v * jv; }
            }
            if (j + 1 < MHN_) {
                float jv = s_invj[cl + 1];
                if (r0 < MHN_) { g_attdot[r0 * MHN_ + j + 1] = acc[n][1]; g_sim[r0 * MHN_ + j + 1] = acc[n][1] * i0v * jv; }
                if (r1 < MHN_) { g_attdot[r1 * MHN_ + j + 1] = acc[n][3]; g_sim[r1 * MHN_ + j + 1] = acc[n][3] * i1v * jv; }
            }
        }
    }
    {
        float m0 = -FLT_MAX, m1 = -FLT_MAX;
#pragma unroll
        for (int n = 0; n < 8; n++) {
            m0 = fmaxf(m0, fmaxf(acc[n][0], acc[n][1]));
            m1 = fmaxf(m1, fmaxf(acc[n][2], acc[n][3]));
        }
        float s0 = 0.f, s1 = 0.f;
#pragma unroll
        for (int n = 0; n < 8; n++) {
            s0 += __expf(acc[n][0] - m0) + __expf(acc[n][1] - m0);
            s1 += __expf(acc[n][2] - m1) + __expf(acc[n][3] - m1);
        }
#pragma unroll
        for (int o = 1; o <= 2; o <<= 1) {
            float mo = __shfl_xor_sync(0xffffffffu, m0, o);
            float so = __shfl_xor_sync(0xffffffffu, s0, o);
            msmerge(m0, s0, mo, so);
            mo = __shfl_xor_sync(0xffffffffu, m1, o);
            so = __shfl_xor_sync(0xffffffffu, s1, o);
            msmerge(m1, s1, mo, so);
        }
        if (t == 0) {
            redm[rbase][wn] = m0; reds[rbase][wn] = s0;
            redm[rbase + 8][wn] = m1; reds[rbase + 8][wn] = s1;
        }
    }
    if (bm < MFN_) {
        float vt0 = s_invi[rbase] * (1.f / TAU_F);
        float vt1 = s_invi[rbase + 8] * (1.f / TAU_F);
        float m2 = -FLT_MAX, s2 = 0.f, m3 = -FLT_MAX, s3 = 0.f;
#pragma unroll
        for (int n = 0; n < 8; n++) {
            int cl = wn * 64 + n * 8 + 2 * t;
            float j0v = s_invj[cl], j1v = s_invj[cl + 1];
            msadd(m2, s2, acc[n][0] * vt0 * j0v);
            msadd(m2, s2, acc[n][1] * vt0 * j1v);
            msadd(m3, s3, acc[n][2] * vt1 * j0v);
            msadd(m3, s3, acc[n][3] * vt1 * j1v);
        }
#pragma unroll
        for (int o = 1; o <= 2; o <<= 1) {
            float mo = __shfl_xor_sync(0xffffffffu, m2, o);
            float so = __shfl_xor_sync(0xffffffffu, s2, o);
            msmerge(m2, s2, mo, so);
            mo = __shfl_xor_sync(0xffffffffu, m3, o);
            so = __shfl_xor_sync(0xffffffffu, s3, o);
            msmerge(m3, s3, mo, so);
        }
        if (t == 0) {
            redm2[rbase][wn] = m2; reds2[rbase][wn] = s2;
            redm2[rbase + 8][wn] = m3; reds2[rbase + 8][wn] = s3;
        }
    }
    __syncthreads();
    if (tid < 64) {
        int i = bm + tid;
        if (i < MHN_) {
            float M = redm[tid][0], S = reds[tid][0];
            msmerge(M, S, redm[tid][1], reds[tid][1]);
            g_attm[i * NSPL_ + sp] = M;
            g_atts[i * NSPL_ + sp] = S;
        }
        if (i < MFN_) {
            float M = redm2[tid][0], S = reds2[tid][0];
            msmerge(M, S, redm2[tid][1], reds2[tid][1]);
            g_lsem[i * NSPL_ + sp] = M;
            g_lses[i * NSPL_ + sp] = S;
        }
    }
}

// cl logits GEMM, inline norms
__global__ void clgemm_kernel() {
    __shared__ float As[16][68];
    __shared__ float Bs[16][132];
    __shared__ float s_invi[64], s_invj[128];
    const int bm = blockIdx.x * 64;
    const int j0 = blockIdx.y * 128;
    const int tid = threadIdx.x;
    const int tx = tid & 15, ty = tid >> 4;
    if (tid < 64) {
        int r = bm + tid;
        float s = g_znpart[0][r] + g_znpart[1][r] + g_znpart[2][r] + g_znpart[3][r];
        s_invi[tid] = 1.f / fmaxf(sqrtf(s), 1e-8f);
    }
    {
        int r = j0 + tid;
        float s = g_hnpart[0][r] + g_hnpart[1][r] + g_hnpart[2][r] + g_hnpart[3][r];
        s_invj[tid] = 1.f / fmaxf(sqrtf(s), 1e-8f);
    }
    float acc[8][8];
#pragma unroll
    for (int r = 0; r < 8; r++)
#pragma unroll
        for (int c = 0; c < 8; c++) acc[r][c] = 0.f;
    for (int k0 = 0; k0 < D_; k0 += 16) {
#pragma unroll
        for (int l = 0; l < 2; l++) {
            int id = tid * 2 + l;
            int r = id >> 2, c4 = id & 3;
            float4 v = *(const float4*)&g_z[(bm + r) * D_ + k0 + c4 * 4];
            As[c4 * 4 + 0][r] = v.x;
            As[c4 * 4 + 1][r] = v.y;
            As[c4 * 4 + 2][r] = v.z;
            As[c4 * 4 + 3][r] = v.w;
        }
#pragma unroll
        for (int l = 0; l < 4; l++) {
            int id = tid + 128 * l;
            int jr = id >> 2, c4 = id & 3;
            float4 v = *(const float4*)&g_hedges[(j0 + jr) * D_ + k0 + c4 * 4];
            Bs[c4 * 4 + 0][jr] = v.x;
            Bs[c4 * 4 + 1][jr] = v.y;
            Bs[c4 * 4 + 2][jr] = v.z;
            Bs[c4 * 4 + 3][jr] = v.w;
        }
        __syncthreads();
#pragma unroll
        for (int kk = 0; kk < 16; kk++) {
            float4 a0 = *(const float4*)&As[kk][ty * 8];
            float4 a1 = *(const float4*)&As[kk][ty * 8 + 4];
            float4 b0 = *(const float4*)&Bs[kk][tx * 8];
            float4 b1 = *(const float4*)&Bs[kk][tx * 8 + 4];
            float a[8] = {a0.x, a0.y, a0.z, a0.w, a1.x, a1.y, a1.z, a1.w};
            float b[8] = {b0.x, b0.y, b0.z, b0.w, b1.x, b1.y, b1.z, b1.w};
#pragma unroll
            for (int r = 0; r < 8; r++)
#pragma unroll
                for (int c = 0; c < 8; c++) acc[r][c] += a[r] * b[c];
        }
        __syncthreads();
    }
#pragma unroll
    for (int r = 0; r < 8; r++) {
        int i = bm + ty * 8 + r;
        if (i >= ECAP_) continue;
        float vi = s_invi[ty * 8 + r] * (1.f / TAU_F);
#pragma unroll
        for (int c = 0; c < 8; c += 2) {
            int j = j0 + tx * 8 + c;
            if (j < ECAP_ - 1) {
                *(float2*)&g_logits[i * 512 + j] =
                    make_float2(acc[r][c] * vi * s_invj[tx * 8 + c],
                                acc[r][c + 1] * vi * s_invj[tx * 8 + c + 1]);
            } else {
                if (j < ECAP_) g_logits[i * 512 + j] = acc[r][c] * vi * s_invj[tx * 8 + c];
                if (j + 1 < ECAP_) g_logits[i * 512 + j + 1] = acc[r][c + 1] * vi * s_invj[tx * 8 + c + 1];
            }
        }
    }
}

// Sparse edge aggregation
__global__ void edge_part_kernel(const float* __restrict__ Hp, const float* __restrict__ z) {
    __shared__ float racc[8][4][256];
    __shared__ int rcnt[8][4];
    const int tid = threadIdx.x;
    const int lane = tid & 31, w = tid >> 5;
    const int e0 = blockIdx.x * 4, sp = blockIdx.y;
    float acc[4][8] = {};
    int cnt[4] = {0, 0, 0, 0};
    const int ibase = sp * 1024;
#pragma unroll 1
    for (int ic = 0; ic < 1024; ic += 256) {
        int i0 = ibase + ic;
        float4 v = *(const float4*)&Hp[(size_t)(i0 + tid) * E_ + e0];
        int m = (v.x > 0.f) | ((v.y > 0.f) << 1) | ((v.z > 0.f) << 2) | ((v.w > 0.f) << 3);
        unsigned b = __ballot_sync(0xffffffffu, m != 0);
        int rowbase = i0 + w * 32;
        while (b) {
            int src = __ffs(b) - 1;
            b &= b - 1;
            int mm = __shfl_sync(0xffffffffu, m, src);
            const float* zr = &z[(size_t)(rowbase + src) * D_];
            float zv[8];
#pragma unroll
            for (int t = 0; t < 8; t++) zv[t] = zr[lane + 32 * t];
            switch (mm) {
                case 1:
#pragma unroll
                    for (int t = 0; t < 8; t++) acc[0][t] += zv[t];
                    cnt[0]++; break;
                case 2:
#pragma unroll
                    for (int t = 0; t < 8; t++) acc[1][t] += zv[t];
                    cnt[1]++; break;
                case 4:
#pragma unroll
                    for (int t = 0; t < 8; t++) acc[2][t] += zv[t];
                    cnt[2]++; break;
                case 8:
#pragma unroll
                    for (int t = 0; t < 8; t++) acc[3][t] += zv[t];
                    cnt[3]++; break;
                default:
                    if (mm & 1) {
#pragma unroll
                        for (int t = 0; t < 8; t++) acc[0][t] += zv[t];
                        cnt[0]++;
                    }
                    if (mm & 2) {
#pragma unroll
                        for (int t = 0; t < 8; t++) acc[1][t] += zv[t];
                        cnt[1]++;
                    }
                    if (mm & 4) {
#pragma unroll
                        for (int t = 0; t < 8; t++) acc[2][t] += zv[t];
                        cnt[2]++;
                    }
                    if (mm & 8) {
#pragma unroll
                        for (int t = 0; t < 8; t++) acc[3][t] += zv[t];
                        cnt[3]++;
                    }
            }
        }
    }
#pragma unroll
    for (int e = 0; e < 4; e++)
#pragma unroll
        for (int t = 0; t < 8; t++) racc[w][e][lane + 32 * t] = acc[e][t];
    if (lane == 0) {
#pragma unroll
        for (int e = 0; e < 4; e++) rcnt[w][e] = cnt[e];
    }
    __syncthreads();
#pragma unroll
    for (int e = 0; e < 4; e++) {
        float s = 0.f;
#pragma unroll
        for (int q = 0; q < 8; q++) s += racc[q][e][tid];
        g_edge_part[sp][(e0 + e) * D_ + tid] = s;
    }
    if (tid < 4) {
        int c = 0;
#pragma unroll
        for (int q = 0; q < 8; q++) c += rcnt[q][tid];
        g_cntp[sp][e0 + tid] = c;
    }
}

// edge MLP layer 1 (mean fused)
__global__ void gemm64_e1_kernel(const float* __restrict__ B, const float* __restrict__ bias,
                                 float* __restrict__ C) {
    __shared__ float As[16][68];
    __shared__ float Bs[16][68];
    const int bm = blockIdx.x * 64, bn = blockIdx.y * 64;
    const int tid = threadIdx.x;
    const int tx = tid & 15, ty = tid >> 4;
    const int arow = bm + (tid >> 2);
    float cinv = 0.f;
    {
        int c = 0;
#pragma unroll
        for (int p = 0; p < 8; p++) c += g_cntp[p][arow];
        cinv = (c > 0 && arow < ECAP_) ? 1.f / (float)c : 0.f;
    }
    float acc[4][4] = {};
    for (int k0 = 0; k0 < D_; k0 += 16) {
        {
            int r = tid >> 2, c4 = tid & 3;
            float4 s = make_float4(0.f, 0.f, 0.f, 0.f);
#pragma unroll
            for (int p = 0; p < 8; p++) {
                float4 t = *(const float4*)&g_edge_part[p][arow * D_ + k0 + c4 * 4];
                s.x += t.x; s.y += t.y; s.z += t.z; s.w += t.w;
            }
            As[c4 * 4 + 0][r] = s.x * cinv;
            As[c4 * 4 + 1][r] = s.y * cinv;
            As[c4 * 4 + 2][r] = s.z * cinv;
            As[c4 * 4 + 3][r] = s.w * cinv;
        }
        {
            int r = tid >> 4, c4 = tid & 15;
            float4 v = *(const float4*)&B[(k0 + r) * D_ + bn + c4 * 4];
            *(float4*)&Bs[r][c4 * 4] = v;
        }
        __syncthreads();
#pragma unroll
        for (int kk = 0; kk < 16; kk++) {
            float a[4], b[4];
#pragma unroll
            for (int u = 0; u < 4; u++) a[u] = As[kk][ty * 4 + u];
#pragma unroll
            for (int u = 0; u < 4; u++) b[u] = Bs[kk][tx * 4 + u];
#pragma unroll
            for (int i = 0; i < 4; i++)
#pragma unroll
                for (int j = 0; j < 4; j++) acc[i][j] += a[i] * b[j];
        }
        __syncthreads();
    }
#pragma unroll
    for (int i = 0; i < 4; i++) {
        int row = bm + ty * 4 + i;
#pragma unroll
        for (int j = 0; j < 4; j++) {
            int col = bn + tx * 4 + j;
            C[row * D_ + col] = fmaxf(acc[i][j] + bias[col], 0.f);
        }
    }
}

// edge MLP layer 2 (hnorm partials fused)
__global__ void gemm64_e2_kernel(const float* __restrict__ A, const float* __restrict__ B,
                                 const float* __restrict__ bias, float* __restrict__ C) {
    __shared__ float As[16][68];
    __shared__ float Bs[16][68];
    __shared__ float ssq[64][17];
    const int bm = blockIdx.x * 64, bn = blockIdx.y * 64;
    const int tid = threadIdx.x;
    const int tx = tid & 15, ty = tid >> 4;
    float acc[4][4] = {};
    for (int k0 = 0; k0 < D_; k0 += 16) {
        {
            int r = tid >> 2, c4 = tid & 3;
            float4 v = *(const float4*)&A[(bm + r) * D_ + k0 + c4 * 4];
            As[c4 * 4 + 0][r] = v.x;
            As[c4 * 4 + 1][r] = v.y;
            As[c4 * 4 + 2][r] = v.z;
            As[c4 * 4 + 3][r] = v.w;
        }
        {
            int r = tid >> 4, c4 = tid & 15;
            float4 v = *(const float4*)&B[(k0 + r) * D_ + bn + c4 * 4];
            *(float4*)&Bs[r][c4 * 4] = v;
        }
        __syncthreads();
#pragma unroll
        for (int kk = 0; kk < 16; kk++) {
            float a[4], b[4];
#pragma unroll
            for (int u = 0; u < 4; u++) a[u] = As[kk][ty * 4 + u];
#pragma unroll
            for (int u = 0; u < 4; u++) b[u] = Bs[kk][tx * 4 + u];
#pragma unroll
            for (int i = 0; i < 4; i++)
#pragma unroll
                for (int j = 0; j < 4; j++) acc[i][j] += a[i] * b[j];
        }
        __syncthreads();
    }
#pragma unroll
    for (int i = 0; i < 4; i++) {
        int row = bm + ty * 4 + i;
        float sq = 0.f;
#pragma unroll
        for (int j = 0; j < 4; j++) {
            int col = bn + tx * 4 + j;
            float v = acc[i][j] + bias[col];
            C[row * D_ + col] = v;
            sq += v * v;
        }
        ssq[ty * 4 + i][tx] = sq;
    }
    __syncthreads();
    if (tid < 64) {
        float s = 0.f;
#pragma unroll
        for (int q = 0; q < 16; q++) s += ssq[tid][q];
        g_hnpart[blockIdx.y][bm + tid] = s;
    }
}

// merged finalize: att rows (0..199), lse (200)
__global__ void merge_kernel() {
    int b = blockIdx.x;
    if (b < MHN_) {
        int i = b;
        __shared__ float Ms, Ss;
        if (threadIdx.x == 0) {
            float M = -FLT_MAX;
            for (int p = 0; p < NSPL_; p++) M = fmaxf(M, g_attm[i * NSPL_ + p]);
            float S = 0.f;
            for (int p = 0; p < NSPL_; p++) S += g_atts[i * NSPL_ + p] * __expf(g_attm[i * NSPL_ + p] - M);
            Ms = M; Ss = S;
        }
        __syncthreads();
        for (int j = threadIdx.x; j < MHN_; j += blockDim.x)
            g_att[i * MHN_ + j] = __expf(g_attdot[i * MHN_ + j] - Ms) / Ss;
    } else {
        int i = threadIdx.x;
        if (i < MFN_) {
            float M = -FLT_MAX;
            for (int p = 0; p < NSPL_; p++) M = fmaxf(M, g_lsem[i * NSPL_ + p]);
            float S = 0.f;
            for (int p = 0; p < NSPL_; p++) S += g_lses[i * NSPL_ + p] * __expf(g_lsem[i * NSPL_ + p] - M);
            g_lse[i] = M + logf(S);
        }
    }
}

// cl losses: one block per row, softmax over precomputed logits
__global__ void losses_cl_kernel() {
    __shared__ float sm[32];
    int i = blockIdx.x;
    int tid = threadIdx.x;
    float lm = -FLT_MAX;
    for (int j = tid; j < ECAP_; j += 256) lm = fmaxf(lm, g_logits[i * 512 + j]);
    float M = block_max(lm, sm);
    float ls = 0.f;
    for (int j = tid; j < ECAP_; j += 256) ls += __expf(g_logits[i * 512 + j] - M);
    float S = block_sum(ls, sm);
    if (tid == 0) g_clrow[i] = g_logits[i * 512 + i] - (M + logf(S));
}

// hn (+fn) losses: one block per row i in [0,200)
__global__ void losses_hn_kernel(const float* __restrict__ Ho, const float* __restrict__ Hp) {
    __shared__ float sm[32];
    int i = blockIdx.x;
    int tid = threadIdx.x;
    {
        int j = tid;
        bool act = j < MHN_;
        float simv = act ? g_sim[i * MHN_ + j] : 0.f;
        float attv = act ? g_att[i * MHN_ + j] : 1.f;
        bool mask = act && (j != i) && (simv > MU_F) && (attv < NU_F);
        float neg = -simv / TAU_F;
        float m = block_max(mask ? neg : -FLT_MAX, sm);
        if (m == -FLT_MAX) {
            if (tid == 0) { g_hnsum[i] = 0.f; g_hncnt[i] = 0.f; }
        } else {
            float s = block_sum(mask ? expf(neg - m) : 0.f, sm);
            float lse = m + logf(s);
            float wgt = fminf(simv / MU_F, 1.f);
            float pair = -wgt * (neg - lse);
            float ps = block_sum(mask ? pair : 0.f, sm);
            float pc = block_sum(mask ? 1.f : 0.f, sm);
            if (tid == 0) { g_hnsum[i] = ps; g_hncnt[i] = pc; }
        }
    }
    if (i < MFN_) {
        __shared__ unsigned char cand[128];
        __shared__ short clist[MFN_];
        __shared__ int ncand;
        if (tid < 128) cand[tid] = 0;
        __syncthreads();
        if (tid < MFN_) {
            bool g = (tid > i) && (g_sim[i * MHN_ + tid] > GAMMA_F)
                               && (g_att[i * MHN_ + tid] > DELTA_F);
            cand[tid] = g ? 1 : 0;
        }
        __syncthreads();
        if (tid == 0) {
            int n = 0;
            for (int j = i + 1; j < MFN_; j++) if (cand[j]) clist[n++] = (short)j;
            ncand = n;
        }
        __syncthreads();
        int nc = ncand;
        float fsum = 0.f, fcnt = 0.f;
        for (int k = 0; k < nc; k++) {
            int j = clist[k];
            float ao = 0.f, ap = 0.f;
            for (int t = tid; t < E_; t += 256) {
                ao += Ho[i * E_ + t] * Ho[j * E_ + t];
                ap += Hp[i * E_ + t] * Hp[j * E_ + t];
            }
            ao = block_sum(ao, sm);
            ap = block_sum(ap, sm);
            if (ap == 0.f && ao > 0.f) {
                fsum += -(g_sim[i * MHN_ + j] / TAU_F - g_lse[i]);
                fcnt += 1.f;
            }
        }
        if (tid == 0) { g_fnrow[i] = fsum; g_fncnt[i] = fcnt; }
    }
}

// final combine
__global__ void final_kernel(const float* __restrict__ bw, float* __restrict__ out) {
    __shared__ float sm[32];
    int tid = threadIdx.x;
    float v = 0.f;
    for (int i = tid; i < ECAP_; i += 512) v += g_clrow[i];
    float clsum = block_sum(v, sm);
    v = 0.f; float c = 0.f;
    for (int i = tid; i < MFN_; i += 512) { v += g_fnrow[i]; c += g_fncnt[i]; }
    float fnsum = block_sum(v, sm);
    float fncnt = block_sum(c, sm);
    v = 0.f; c = 0.f;
    for (int i = tid; i < MHN_; i += 512) { v += g_hnsum[i]; c += g_hncnt[i]; }
    float hnsum = block_sum(v, sm);
    float hncnt = block_sum(c, sm);
    float d2 = 0.f, o2 = 0.f;
    for (int i = tid; i < SAMP_; i += 512) { d2 += g_topo[i * 2]; o2 += g_topo[i * 2 + 1]; }
    float D2 = block_sum(d2, sm);
    float O2 = block_sum(o2, sm);
    float za = 0.f, zb = 0.f;
    for (int i = tid; i < 2048; i += 512) { za += (float)g_nza[i]; zb += (float)g_nzb[i]; }
    float NZ = block_sum(za, sm);
    float NZP = block_sum(zb, sm);
    if (tid == 0) {
        float cl_loss = -clsum / (float)ECAP_;
        float fn_loss = (fncnt > 0.f) ? fnsum / fmaxf(fncnt, 1.f) : 0.f;
        float hard_loss = (hncnt > 0.f) ? hnsum / fmaxf(hncnt, 1.f) : 0.f;
        float sparsity = (NZ > 0.f) ? NZP / fmaxf(NZ, 1.f) : 1.f;
        float dn = sqrtf(D2), on = sqrtf(O2);
        float topo = (on > 0.f) ? expf(-ALPHA_F * dn / fmaxf(on, 1e-12f)) : 1.f;
        float retention = sparsity * topo;
        out[0] = bw[0] * (retention * cl_loss + fn_loss + hard_loss);
    }
}

// ---------------- launch (fork/join streams) ----------------
extern "C" void kernel_launch(void* const* d_in, const int* in_sizes, int n_in,
                              void* d_out, int out_size) {
    (void)in_sizes; (void)n_in; (void)out_size;
    const float* Ho  = (const float*)d_in[0];
    const float* Hp  = (const float*)d_in[1];
    const float* ne  = (const float*)d_in[2];
    const float* bw  = (const float*)d_in[3];
    const float* Wn1 = (const float*)d_in[4];
    const float* bn1 = (const float*)d_in[5];
    const float* Wn2 = (const float*)d_in[6];
    const float* bn2 = (const float*)d_in[7];
    const float* We1 = (const float*)d_in[8];
    const float* be1 = (const float*)d_in[9];
    const float* We2 = (const float*)d_in[10];
    const float* be2 = (const float*)d_in[11];
    float* out = (float*)d_out;

    void *p;
    float *p_tmp, *p_z, *p_etmp, *p_hedges;
    cudaGetSymbolAddress(&p, g_tmp);    p_tmp    = (float*)p;
    cudaGetSymbolAddress(&p, g_z);      p_z      = (float*)p;
    cudaGetSymbolAddress(&p, g_etmp);   p_etmp   = (float*)p;
    cudaGetSymbolAddress(&p, g_hedges); p_hedges = (float*)p;

    static cudaStream_t s1, s2;
    static cudaEvent_t evRoot, evZ, evE, evC;
    static int inited = 0;
    if (!inited) {
        cudaStreamCreateWithFlags(&s1, cudaStreamNonBlocking);
        cudaStreamCreateWithFlags(&s2, cudaStreamNonBlocking);
        cudaEventCreateWithFlags(&evRoot, cudaEventDisableTiming);
        cudaEventCreateWithFlags(&evZ,   cudaEventDisableTiming);
        cudaEventCreateWithFlags(&evE,   cudaEventDisableTiming);
        cudaEventCreateWithFlags(&evC,   cudaEventDisableTiming);
        inited = 1;
    }

    // fork s2 at entry: independent H scans (short kernel first)
    cudaEventRecord(evRoot, 0);
    cudaStreamWaitEvent(s2, evRoot, 0);
    topo_kernel<<<SAMP_, 128, 0, s2>>>(Ho, Hp);
    count_nz_kernel<<<2048, 256, 0, s2>>>((const float4*)Ho, (const float4*)Hp);
    cudaEventRecord(evC, s2);

    // main chain: node MLP
    gemm_tf32_kernel<true,  false><<<dim3(64, 4), 256>>>(ne,    Wn1, bn1, p_tmp);
    gemm_tf32_kernel<false, true ><<<dim3(64, 4), 256>>>(p_tmp, Wn2, bn2, p_z);

    // fork s1 after z: edge path + cl losses
    cudaEventRecord(evZ, 0);
    cudaStreamWaitEvent(s1, evZ, 0);
    edge_part_kernel<<<dim3(ECAP_ / 4, 8), 256, 0, s1>>>(Hp, p_z);
    gemm64_e1_kernel<<<dim3(8, 4), 256, 0, s1>>>(We1, be1, p_etmp);
    gemm64_e2_kernel<<<dim3(8, 4), 256, 0, s1>>>(p_etmp, We2, be2, p_hedges);
    clgemm_kernel<<<dim3(8, 4), 128, 0, s1>>>();
    losses_cl_kernel<<<ECAP_, 256, 0, s1>>>();
    cudaEventRecord(evE, s1);

    // main chain continues: attention path + hn/fn losses
    attgemm_kernel<<<dim3(4, NSPL_), 256>>>();
    merge_kernel<<<MHN_ + 1, 256>>>();
    losses_hn_kernel<<<MHN_, 256>>>(Ho, Hp);

    // join all branches, then final
    cudaStreamWaitEvent(0, evE, 0);
    cudaStreamWaitEvent(0, evC, 0);
    final_kernel<<<1, 512>>>(bw, out);
}